// round 2
// baseline (speedup 1.0000x reference)
#include <cuda_runtime.h>
#include <math.h>

// Problem constants (fixed shapes)
constexpr int BATCH = 8;
constexpr int DIM   = 384;
constexpr int NH    = 8;     // heads
constexpr int CH    = 48;    // channels per head
constexpr int HWD   = 16384; // 128*128
constexpr int C3    = 1152;  // 3*DIM
constexpr int TOPKN = 7;

// Scratch (device globals: allocation-free rule)
__device__ float g_qkv1[(size_t)BATCH * C3 * HWD];   // after 1x1 conv
__device__ float g_qkv2[(size_t)BATCH * C3 * HWD];   // after depthwise 3x3
__device__ float g_inv[2 * BATCH * DIM];             // inv norms: [q rows | k rows]
__device__ float g_gpart[8 * BATCH * NH * CH * CH];  // partial Gram sums (8 n-chunks)
__device__ float g_attn[BATCH * NH * CH * CH];       // attention after softmax
__device__ float g_Wb[BATCH * DIM * DIM];            // proj_w @ blockdiag(attn)

// ---------------------------------------------------------------------------
// Generic batched SGEMM: C[M,N] = A[M,K] @ B[K,N], 64x64 tile, BK=16, 256 thr
// M, N, K all multiples of 64/64/16 here, no bounds checks needed.
// ---------------------------------------------------------------------------
__global__ void sgemm64(const float* __restrict__ A, const float* __restrict__ Bm,
                        float* __restrict__ C, int N, int K,
                        long sA, long sB, long sC)
{
    A  += (long)blockIdx.z * sA;
    Bm += (long)blockIdx.z * sB;
    C  += (long)blockIdx.z * sC;

    __shared__ float As[16][64];
    __shared__ float Bs[16][64];

    const int tid = threadIdx.x;
    const int tx = tid & 15, ty = tid >> 4;
    const int row0 = blockIdx.y * 64, col0 = blockIdx.x * 64;

    float acc[4][4] = {};

    for (int k0 = 0; k0 < K; k0 += 16) {
#pragma unroll
        for (int i = 0; i < 4; i++) {
            int idx = tid + i * 256;                 // 0..1023
            As[idx & 15][idx >> 4] = A[(long)(row0 + (idx >> 4)) * K + k0 + (idx & 15)];
            Bs[idx >> 6][idx & 63] = Bm[(long)(k0 + (idx >> 6)) * N + col0 + (idx & 63)];
        }
        __syncthreads();
#pragma unroll
        for (int kk = 0; kk < 16; kk++) {
            float a[4], b[4];
#pragma unroll
            for (int i = 0; i < 4; i++) a[i] = As[kk][ty * 4 + i];
#pragma unroll
            for (int j = 0; j < 4; j++) b[j] = Bs[kk][tx * 4 + j];
#pragma unroll
            for (int i = 0; i < 4; i++)
#pragma unroll
                for (int j = 0; j < 4; j++)
                    acc[i][j] += a[i] * b[j];
        }
        __syncthreads();
    }
#pragma unroll
    for (int i = 0; i < 4; i++)
#pragma unroll
        for (int j = 0; j < 4; j++)
            C[(long)(row0 + ty * 4 + i) * N + col0 + tx * 4 + j] = acc[i][j];
}

// ---------------------------------------------------------------------------
// Depthwise 3x3, pad 1, H=W=128
// ---------------------------------------------------------------------------
__global__ void dwconv3(const float* __restrict__ in, const float* __restrict__ w,
                        float* __restrict__ out)
{
    int c = blockIdx.y;
    int b = blockIdx.z;
    int p = blockIdx.x * 256 + threadIdx.x;   // pixel 0..16383
    int h = p >> 7, x = p & 127;
    const float* ip = in + ((long)b * C3 + c) * HWD;
    const float* wp = w + c * 9;
    float s = 0.f;
#pragma unroll
    for (int dy = -1; dy <= 1; dy++) {
        int hh = h + dy;
        if (hh < 0 || hh >= 128) continue;
#pragma unroll
        for (int dx = -1; dx <= 1; dx++) {
            int xx = x + dx;
            if (xx < 0 || xx >= 128) continue;
            s += wp[(dy + 1) * 3 + (dx + 1)] * ip[hh * 128 + xx];
        }
    }
    out[((long)b * C3 + c) * HWD + p] = s;
}

// ---------------------------------------------------------------------------
// Per-row inverse L2 norm for q (rows 0..3071) and k (rows 3072..6143)
// ---------------------------------------------------------------------------
__global__ void rownorm(const float* __restrict__ qkv2, float* __restrict__ inv)
{
    int rid = blockIdx.x;                 // 0..2*BATCH*DIM-1
    int isK = rid >= BATCH * DIM;
    int r = isK ? rid - BATCH * DIM : rid;
    int b = r / DIM, c = r % DIM;
    const float* p = qkv2 + ((long)b * C3 + (isK ? DIM : 0) + c) * HWD;
    float s = 0.f;
    for (int i = threadIdx.x; i < HWD; i += 256) { float v = p[i]; s += v * v; }
    __shared__ float red[256];
    red[threadIdx.x] = s;
    __syncthreads();
    for (int st = 128; st > 0; st >>= 1) {
        if (threadIdx.x < st) red[threadIdx.x] += red[threadIdx.x + st];
        __syncthreads();
    }
    if (threadIdx.x == 0) {
        float n = sqrtf(red[0]);
        inv[rid] = 1.f / fmaxf(n, 1e-12f);
    }
}

// ---------------------------------------------------------------------------
// Gram partial: for each (b,h), chunk of n: S[c,d] += q_c . k_d  (48x48)
// grid = (8 chunks, 64 bh), 256 threads, 3x3 outputs per thread
// ---------------------------------------------------------------------------
__global__ void gram_partial(const float* __restrict__ qkv2, float* __restrict__ gpart)
{
    int chunk = blockIdx.x;               // 0..7
    int bh = blockIdx.y;                  // 0..63
    int b = bh >> 3, h = bh & 7;
    const float* qb = qkv2 + ((long)b * C3 + h * CH) * HWD;
    const float* kb = qb + (long)DIM * HWD;

    __shared__ float qs[48][33], ks[48][33];
    const int tid = threadIdx.x;
    const int tx = tid & 15, ty = tid >> 4;
    float acc[3][3] = {};

    const int n0base = chunk * (HWD / 8);
    for (int n0 = n0base; n0 < n0base + HWD / 8; n0 += 32) {
#pragma unroll
        for (int i = 0; i < 6; i++) {
            int idx = tid + i * 256;      // 0..1535
            int r = idx >> 5, t = idx & 31;
            qs[r][t] = qb[(long)r * HWD + n0 + t];
            ks[r][t] = kb[(long)r * HWD + n0 + t];
        }
        __syncthreads();
#pragma unroll
        for (int t = 0; t < 32; t++) {
            float qa[3], ka[3];
#pragma unroll
            for (int i = 0; i < 3; i++) qa[i] = qs[ty * 3 + i][t];
#pragma unroll
            for (int j = 0; j < 3; j++) ka[j] = ks[tx * 3 + j][t];
#pragma unroll
            for (int i = 0; i < 3; i++)
#pragma unroll
                for (int j = 0; j < 3; j++)
                    acc[i][j] += qa[i] * ka[j];
        }
        __syncthreads();
    }
    float* op = gpart + ((long)chunk * 64 + bh) * (CH * CH);
#pragma unroll
    for (int i = 0; i < 3; i++)
#pragma unroll
        for (int j = 0; j < 3; j++)
            op[(ty * 3 + i) * CH + tx * 3 + j] = acc[i][j];
}

// ---------------------------------------------------------------------------
// Reduce partials + apply inv norms * temperature
// ---------------------------------------------------------------------------
__global__ void gram_scale(const float* __restrict__ gpart, const float* __restrict__ inv,
                           const float* __restrict__ temp, float* __restrict__ attn)
{
    int idx = blockIdx.x * 256 + threadIdx.x;   // < 64*2304
    if (idx >= 64 * CH * CH) return;
    int bh = idx / (CH * CH), r = idx % (CH * CH);
    int c = r / CH, d = r % CH;
    int b = bh >> 3, h = bh & 7;
    float s = 0.f;
#pragma unroll
    for (int ck = 0; ck < 8; ck++) s += gpart[((long)ck * 64 + bh) * (CH * CH) + r];
    float iq = inv[b * DIM + h * CH + c];
    float ik = inv[BATCH * DIM + b * DIM + h * CH + d];
    attn[idx] = s * iq * ik * temp[h];
}

// ---------------------------------------------------------------------------
// Top-7 mask + softmax per row of 48 (distinct values => rank test is exact)
// ---------------------------------------------------------------------------
__global__ void topk_softmax(float* __restrict__ attn)
{
    int row = blockIdx.x;                // 0..3071
    float* p = attn + (long)row * CH;
    __shared__ float s[CH], e[CH];
    int i = threadIdx.x;
    if (i < CH) s[i] = p[i];
    __syncthreads();
    if (i < CH) {
        float v = s[i];
        int cnt = 0;
        float m = -1e30f;
#pragma unroll
        for (int j = 0; j < CH; j++) {
            cnt += (s[j] > v);
            m = fmaxf(m, s[j]);
        }
        e[i] = (cnt < TOPKN) ? expf(v - m) : 0.f;
    }
    __syncthreads();
    if (i < CH) {
        float sum = 0.f;
#pragma unroll
        for (int j = 0; j < CH; j++) sum += e[j];
        p[i] = e[i] / sum;
    }
}

// ---------------------------------------------------------------------------
// Fold: Wb[b][o][dg] = sum_c proj_w[o][h*48+c] * attn[b][h][c][d],  dg=h*48+d
// ---------------------------------------------------------------------------
__global__ void fold_proj(const float* __restrict__ projw, const float* __restrict__ attn,
                          float* __restrict__ Wb)
{
    int idx = blockIdx.x * 256 + threadIdx.x;   // < 8*384*384
    if (idx >= BATCH * DIM * DIM) return;
    int b = idx / (DIM * DIM);
    int r = idx % (DIM * DIM);
    int o = r / DIM, dg = r % DIM;
    int h = dg / CH, d = dg % CH;
    const float* pw = projw + o * DIM + h * CH;
    const float* at = attn + (((long)(b * NH + h)) * CH) * CH + d;
    float s = 0.f;
#pragma unroll
    for (int c = 0; c < CH; c++) s += pw[c] * at[c * CH];
    Wb[idx] = s;
}

// ---------------------------------------------------------------------------
extern "C" void kernel_launch(void* const* d_in, const int* in_sizes, int n_in,
                              void* d_out, int out_size)
{
    const float* x      = (const float*)d_in[0];
    const float* qkv_w  = (const float*)d_in[1];
    const float* dw_w   = (const float*)d_in[2];
    const float* proj_w = (const float*)d_in[3];
    const float* temp   = (const float*)d_in[4];
    float* out = (float*)d_out;

    float *qkv1, *qkv2, *inv, *gpart, *attn, *Wb;
    cudaGetSymbolAddress((void**)&qkv1,  g_qkv1);
    cudaGetSymbolAddress((void**)&qkv2,  g_qkv2);
    cudaGetSymbolAddress((void**)&inv,   g_inv);
    cudaGetSymbolAddress((void**)&gpart, g_gpart);
    cudaGetSymbolAddress((void**)&attn,  g_attn);
    cudaGetSymbolAddress((void**)&Wb,    g_Wb);

    // 1) qkv = qkv_w @ x    (M=1152, K=384, N=16384, batched over 8)
    sgemm64<<<dim3(HWD / 64, C3 / 64, BATCH), 256>>>(
        qkv_w, x, qkv1, HWD, DIM,
        0L, (long)DIM * HWD, (long)C3 * HWD);

    // 2) depthwise 3x3
    dwconv3<<<dim3(HWD / 256, C3, BATCH), 256>>>(qkv1, dw_w, qkv2);

    // 3) inverse L2 norms of q and k rows
    rownorm<<<2 * BATCH * DIM, 256>>>(qkv2, inv);

    // 4) Gram matrices (partial over 8 n-chunks, then reduce+scale)
    gram_partial<<<dim3(8, BATCH * NH), 256>>>(qkv2, gpart);
    gram_scale<<<(64 * CH * CH + 255) / 256, 256>>>(gpart, inv, temp, attn);

    // 5) top-7 + masked softmax
    topk_softmax<<<BATCH * NH * CH, 64>>>(attn);

    // 6) fold proj_w @ blockdiag(attn) -> Wb  (tiny)
    fold_proj<<<(BATCH * DIM * DIM + 255) / 256, 256>>>(proj_w, attn, Wb);

    // 7) out = Wb @ v   (M=384, K=384, N=16384, batched; v = channels 768..1151)
    sgemm64<<<dim3(HWD / 64, DIM / 64, BATCH), 256>>>(
        Wb, qkv2 + (size_t)2 * DIM * HWD, out, HWD, DIM,
        (long)DIM * DIM, (long)C3 * HWD, (long)DIM * HWD);
}

// round 4
// speedup vs baseline: 2.9553x; 2.9553x over previous
#include <cuda_runtime.h>
#include <cuda_bf16.h>
#include <math.h>
#include <stdint.h>

// ---------------------------------------------------------------------------
// Problem constants
// ---------------------------------------------------------------------------
constexpr int BATCH = 8;
constexpr int DIM   = 384;
constexpr int NH    = 8;
constexpr int CH    = 48;
constexpr int HWD   = 16384;  // 128*128
constexpr int C3    = 1152;
constexpr int TOPKN = 7;

// split-precision GEMM constants
constexpr int KP     = 1152;  // K' = 3*384 (hi*hi, lo*hi, hi*lo)
constexpr int KC     = 64;    // k per chunk (128 bytes bf16)
constexpr int NCHUNK = KP / KC;  // 18
constexpr int BM     = 128;
constexpr int BN     = 128;
constexpr int ATILE  = BM * 128;            // bytes per A stage (128B rows)
constexpr int BTILE  = BN * 128;
constexpr int STAGE  = ATILE + BTILE;       // 32 KB
constexpr int NSTAGE = 3;
constexpr int GEMM_SMEM = NSTAGE * STAGE;   // 96 KB

// ---------------------------------------------------------------------------
// Scratch (device globals)
// ---------------------------------------------------------------------------
__device__ float g_qkv1[(size_t)BATCH * C3 * HWD];
__device__ float g_qkv2[(size_t)BATCH * C3 * HWD];
__device__ float g_inv[2 * BATCH * DIM];
__device__ float g_gpart[8 * BATCH * NH * CH * CH];
__device__ float g_attn[BATCH * NH * CH * CH];
__device__ __nv_bfloat16 g_A1[(size_t)C3 * KP];           // qkv_w split [1152][1152]
__device__ __nv_bfloat16 g_xs[(size_t)BATCH * HWD * 768]; // x split-T [b][hw][hi|lo]
__device__ __nv_bfloat16 g_vs[(size_t)BATCH * HWD * 768]; // v split-T
__device__ __nv_bfloat16 g_Wbs[(size_t)BATCH * DIM * KP]; // folded proj split

// ---------------------------------------------------------------------------
// sm_80-portable PTX helpers
// ---------------------------------------------------------------------------
__device__ __forceinline__ uint32_t smem_u32(const void* p) {
    uint32_t a;
    asm("{ .reg .u64 t; cvta.to.shared.u64 t, %1; cvt.u32.u64 %0, t; }" : "=r"(a) : "l"(p));
    return a;
}

__device__ __forceinline__ void cp16(uint32_t saddr, const void* gaddr) {
    asm volatile("cp.async.cg.shared.global [%0], [%1], 16;" :: "r"(saddr), "l"(gaddr));
}
#define CP_COMMIT() asm volatile("cp.async.commit_group;" ::: "memory")

__device__ __forceinline__ void ldmx4(uint32_t* r, uint32_t addr) {
    asm volatile("ldmatrix.sync.aligned.m8n8.x4.shared.b16 {%0,%1,%2,%3}, [%4];"
                 : "=r"(r[0]), "=r"(r[1]), "=r"(r[2]), "=r"(r[3]) : "r"(addr));
}

__device__ __forceinline__ void mma16816(float* c, const uint32_t* a, const uint32_t* b) {
    asm volatile(
        "mma.sync.aligned.m16n8k16.row.col.f32.bf16.bf16.f32 "
        "{%0,%1,%2,%3}, {%4,%5,%6,%7}, {%8,%9}, {%0,%1,%2,%3};"
        : "+f"(c[0]), "+f"(c[1]), "+f"(c[2]), "+f"(c[3])
        : "r"(a[0]), "r"(a[1]), "r"(a[2]), "r"(a[3]), "r"(b[0]), "r"(b[1]));
}

// ---------------------------------------------------------------------------
// Split-precision bf16 tensor-core GEMM:
//   C[bz][m][n] (fp32, row stride HWD) = sum_{k'=0..1151} A'[m][k'] * B'[bz][n][seg(k')]
// A' rows are [hi | lo | hi] (KP columns); B rows are [hi(384) | lo(384)] (768 cols).
// Chunk->B column map: c<6 -> c*64 (hi); 6<=c<12 -> c*64-384 (hi); c>=12 -> c*64-384 (lo)
// ---------------------------------------------------------------------------
__global__ void __launch_bounds__(256, 2)
gemm_split(const __nv_bfloat16* __restrict__ A, long aBatchStride,
           const __nv_bfloat16* __restrict__ B,
           float* __restrict__ C, long cBatchStride)
{
    extern __shared__ char sm[];
    const uint32_t smBase = smem_u32(sm);

    const int tid = threadIdx.x;
    const int wid = tid >> 5, l = tid & 31;
    const int wm = wid >> 2, wn = wid & 3;          // 2 x 4 warp grid
    const int bm0 = blockIdx.x * BM;
    const int bn0 = blockIdx.y * BN;
    const int bz  = blockIdx.z;

    const __nv_bfloat16* Ab = A + (long)bz * aBatchStride + (long)bm0 * KP;
    const __nv_bfloat16* Bb = B + ((long)bz * HWD + bn0) * 768;
    float* Cb = C + (long)bz * cBatchStride + (long)bm0 * HWD + bn0;

    // per-thread cp.async mapping: id = tid + i*256; row = id>>3, q = id&7
    const int ldr = tid >> 3, ldq = tid & 7;

    auto load_chunk = [&](int c, int s) {
        const uint32_t sA = smBase + s * STAGE;
        const uint32_t sB = sA + ATILE;
        const __nv_bfloat16* ac = Ab + c * KC;
        const int bk = (c < 6) ? c * KC : c * KC - 384;
        const __nv_bfloat16* bc = Bb + bk;
#pragma unroll
        for (int i = 0; i < 4; i++) {
            int r = ldr + i * 32;
            int u = ldq ^ (r & 7);
            cp16(sA + r * 128 + u * 16, ac + (long)r * KP + ldq * 8);
        }
#pragma unroll
        for (int i = 0; i < 4; i++) {
            int r = ldr + i * 32;
            int u = ldq ^ (r & 7);
            cp16(sB + r * 128 + u * 16, bc + (long)r * 768 + ldq * 8);
        }
        CP_COMMIT();
    };

    float acc[4][4][4] = {};

    // ldmatrix per-thread address components
    const int l7 = l & 7;
    const int a_x = l >> 4;                         // k half for A
    const int b_x = (l >> 3) & 1;                   // k half for B
    int arow[4], bnrow[2];
#pragma unroll
    for (int mi = 0; mi < 4; mi++)
        arow[mi] = (wm * 64 + mi * 16 + (l & 15)) * 128;
#pragma unroll
    for (int g = 0; g < 2; g++)
        bnrow[g] = (wn * 32 + g * 16 + (l >> 4) * 8 + (l & 7)) * 128;

    load_chunk(0, 0);
    load_chunk(1, 1);

    for (int c = 0; c < NCHUNK; c++) {
        if (c + 2 < NCHUNK) {
            asm volatile("cp.async.wait_group 1;" ::: "memory");
        } else {
            asm volatile("cp.async.wait_group 0;" ::: "memory");
        }
        __syncthreads();
        if (c + 2 < NCHUNK) load_chunk(c + 2, (c + 2) % NSTAGE);

        const int s = c % NSTAGE;
        const uint32_t sA = smBase + s * STAGE;
        const uint32_t sB = sA + ATILE;

#pragma unroll
        for (int kk = 0; kk < 4; kk++) {
            uint32_t afr[4][4];
#pragma unroll
            for (int mi = 0; mi < 4; mi++) {
                uint32_t u = (uint32_t)((kk * 2 + a_x) ^ l7);
                ldmx4(afr[mi], sA + arow[mi] + u * 16);
            }
            uint32_t bfr[4][2];
#pragma unroll
            for (int g = 0; g < 2; g++) {
                uint32_t t4[4];
                uint32_t u = (uint32_t)((kk * 2 + b_x) ^ l7);
                ldmx4(t4, sB + bnrow[g] + u * 16);
                bfr[2 * g][0] = t4[0]; bfr[2 * g][1] = t4[1];
                bfr[2 * g + 1][0] = t4[2]; bfr[2 * g + 1][1] = t4[3];
            }
#pragma unroll
            for (int mi = 0; mi < 4; mi++)
#pragma unroll
                for (int ni = 0; ni < 4; ni++)
                    mma16816(acc[mi][ni], afr[mi], bfr[ni]);
        }
        __syncthreads();
    }

    // epilogue: direct fp32 stores
    const int crow = l >> 2, ccol = (l & 3) * 2;
#pragma unroll
    for (int mi = 0; mi < 4; mi++) {
#pragma unroll
        for (int ni = 0; ni < 4; ni++) {
            float* p = Cb + (long)(wm * 64 + mi * 16 + crow) * HWD + wn * 32 + ni * 8 + ccol;
            *(float2*)p = make_float2(acc[mi][ni][0], acc[mi][ni][1]);
            *(float2*)(p + 8L * HWD) = make_float2(acc[mi][ni][2], acc[mi][ni][3]);
        }
    }
}

// ---------------------------------------------------------------------------
// Split qkv_w -> A' [1152][1152] bf16 = [hi | lo | hi]
// ---------------------------------------------------------------------------
__global__ void split_w(const float* __restrict__ w, __nv_bfloat16* __restrict__ o)
{
    int idx = blockIdx.x * 256 + threadIdx.x;
    if (idx >= C3 * DIM) return;
    int m = idx / DIM, k = idx % DIM;
    float v = w[idx];
    __nv_bfloat16 hi = __float2bfloat16(v);
    __nv_bfloat16 lo = __float2bfloat16(v - __bfloat162float(hi));
    o[(long)m * KP + k]       = hi;
    o[(long)m * KP + 384 + k] = lo;
    o[(long)m * KP + 768 + k] = hi;
}

// ---------------------------------------------------------------------------
// Split + transpose: src [b][384][HWD] fp32 -> dst [b][HWD][hi(384)|lo(384)] bf16
// ---------------------------------------------------------------------------
__global__ void split_t(const float* __restrict__ src, long bstride,
                        __nv_bfloat16* __restrict__ dst)
{
    __shared__ float t[32][33];
    int n0 = blockIdx.x * 32, c0 = blockIdx.y * 32, b = blockIdx.z;
    int tx = threadIdx.x, ty = threadIdx.y;
    const float* s = src + (long)b * bstride;
#pragma unroll
    for (int i = 0; i < 4; i++) {
        int cl = ty + i * 8;
        t[cl][tx] = s[(long)(c0 + cl) * HWD + n0 + tx];
    }
    __syncthreads();
    __nv_bfloat16* d = dst + (long)b * HWD * 768;
#pragma unroll
    for (int i = 0; i < 4; i++) {
        int nr = ty + i * 8;
        float v = t[tx][nr];
        __nv_bfloat16 hi = __float2bfloat16(v);
        __nv_bfloat16 lo = __float2bfloat16(v - __bfloat162float(hi));
        d[(long)(n0 + nr) * 768 + c0 + tx]       = hi;
        d[(long)(n0 + nr) * 768 + 384 + c0 + tx] = lo;
    }
}

// ---------------------------------------------------------------------------
// Depthwise 3x3, pad 1
// ---------------------------------------------------------------------------
__global__ void dwconv3(const float* __restrict__ in, const float* __restrict__ w,
                        float* __restrict__ out)
{
    int c = blockIdx.y;
    int b = blockIdx.z;
    int p = blockIdx.x * 256 + threadIdx.x;
    int h = p >> 7, x = p & 127;
    const float* ip = in + ((long)b * C3 + c) * HWD;
    const float* wp = w + c * 9;
    float s = 0.f;
#pragma unroll
    for (int dy = -1; dy <= 1; dy++) {
        int hh = h + dy;
        if (hh < 0 || hh >= 128) continue;
#pragma unroll
        for (int dx = -1; dx <= 1; dx++) {
            int xx = x + dx;
            if (xx < 0 || xx >= 128) continue;
            s += wp[(dy + 1) * 3 + (dx + 1)] * ip[hh * 128 + xx];
        }
    }
    out[((long)b * C3 + c) * HWD + p] = s;
}

// ---------------------------------------------------------------------------
// Per-row inverse L2 norm
// ---------------------------------------------------------------------------
__global__ void rownorm(const float* __restrict__ qkv2, float* __restrict__ inv)
{
    int rid = blockIdx.x;
    int isK = rid >= BATCH * DIM;
    int r = isK ? rid - BATCH * DIM : rid;
    int b = r / DIM, c = r % DIM;
    const float* p = qkv2 + ((long)b * C3 + (isK ? DIM : 0) + c) * HWD;
    float s = 0.f;
    for (int i = threadIdx.x; i < HWD; i += 256) { float v = p[i]; s += v * v; }
    __shared__ float red[256];
    red[threadIdx.x] = s;
    __syncthreads();
    for (int st = 128; st > 0; st >>= 1) {
        if (threadIdx.x < st) red[threadIdx.x] += red[threadIdx.x + st];
        __syncthreads();
    }
    if (threadIdx.x == 0) {
        float n = sqrtf(red[0]);
        inv[rid] = 1.f / fmaxf(n, 1e-12f);
    }
}

// ---------------------------------------------------------------------------
// Gram partial + scale + topk softmax
// ---------------------------------------------------------------------------
__global__ void gram_partial(const float* __restrict__ qkv2, float* __restrict__ gpart)
{
    int chunk = blockIdx.x;
    int bh = blockIdx.y;
    int b = bh >> 3, h = bh & 7;
    const float* qb = qkv2 + ((long)b * C3 + h * CH) * HWD;
    const float* kb = qb + (long)DIM * HWD;

    __shared__ float qs[48][33], ks[48][33];
    const int tid = threadIdx.x;
    const int tx = tid & 15, ty = tid >> 4;
    float acc[3][3] = {};

    const int n0base = chunk * (HWD / 8);
    for (int n0 = n0base; n0 < n0base + HWD / 8; n0 += 32) {
#pragma unroll
        for (int i = 0; i < 6; i++) {
            int idx = tid + i * 256;
            int r = idx >> 5, t = idx & 31;
            qs[r][t] = qb[(long)r * HWD + n0 + t];
            ks[r][t] = kb[(long)r * HWD + n0 + t];
        }
        __syncthreads();
#pragma unroll
        for (int t = 0; t < 32; t++) {
            float qa[3], ka[3];
#pragma unroll
            for (int i = 0; i < 3; i++) qa[i] = qs[ty * 3 + i][t];
#pragma unroll
            for (int j = 0; j < 3; j++) ka[j] = ks[tx * 3 + j][t];
#pragma unroll
            for (int i = 0; i < 3; i++)
#pragma unroll
                for (int j = 0; j < 3; j++)
                    acc[i][j] += qa[i] * ka[j];
        }
        __syncthreads();
    }
    float* op = gpart + ((long)chunk * 64 + bh) * (CH * CH);
#pragma unroll
    for (int i = 0; i < 3; i++)
#pragma unroll
        for (int j = 0; j < 3; j++)
            op[(ty * 3 + i) * CH + tx * 3 + j] = acc[i][j];
}

__global__ void gram_scale(const float* __restrict__ gpart, const float* __restrict__ inv,
                           const float* __restrict__ temp, float* __restrict__ attn)
{
    int idx = blockIdx.x * 256 + threadIdx.x;
    if (idx >= 64 * CH * CH) return;
    int bh = idx / (CH * CH), r = idx % (CH * CH);
    int c = r / CH, d = r % CH;
    int b = bh >> 3, h = bh & 7;
    float s = 0.f;
#pragma unroll
    for (int ck = 0; ck < 8; ck++) s += gpart[((long)ck * 64 + bh) * (CH * CH) + r];
    float iq = inv[b * DIM + h * CH + c];
    float ik = inv[BATCH * DIM + b * DIM + h * CH + d];
    attn[idx] = s * iq * ik * temp[h];
}

__global__ void topk_softmax(float* __restrict__ attn)
{
    int row = blockIdx.x;
    float* p = attn + (long)row * CH;
    __shared__ float s[CH], e[CH];
    int i = threadIdx.x;
    if (i < CH) s[i] = p[i];
    __syncthreads();
    if (i < CH) {
        float v = s[i];
        int cnt = 0;
        float m = -1e30f;
#pragma unroll
        for (int j = 0; j < CH; j++) {
            cnt += (s[j] > v);
            m = fmaxf(m, s[j]);
        }
        e[i] = (cnt < TOPKN) ? expf(v - m) : 0.f;
    }
    __syncthreads();
    if (i < CH) {
        float sum = 0.f;
#pragma unroll
        for (int j = 0; j < CH; j++) sum += e[j];
        p[i] = e[i] / sum;
    }
}

// ---------------------------------------------------------------------------
// Fold proj_w @ blockdiag(attn) -> Wbs (bf16 split [hi|lo|hi])
// ---------------------------------------------------------------------------
__global__ void fold_proj(const float* __restrict__ projw, const float* __restrict__ attn,
                          __nv_bfloat16* __restrict__ Wbs)
{
    int idx = blockIdx.x * 256 + threadIdx.x;
    if (idx >= BATCH * DIM * DIM) return;
    int b = idx / (DIM * DIM);
    int r = idx % (DIM * DIM);
    int o = r / DIM, dg = r % DIM;
    int h = dg / CH, d = dg % CH;
    const float* pw = projw + o * DIM + h * CH;
    const float* at = attn + ((long)(b * NH + h) * CH) * CH + d;
    float s = 0.f;
#pragma unroll
    for (int c = 0; c < CH; c++) s += pw[c] * at[c * CH];
    __nv_bfloat16 hi = __float2bfloat16(s);
    __nv_bfloat16 lo = __float2bfloat16(s - __bfloat162float(hi));
    __nv_bfloat16* row = Wbs + ((long)b * DIM + o) * KP;
    row[dg]       = hi;
    row[384 + dg] = lo;
    row[768 + dg] = hi;
}

// ---------------------------------------------------------------------------
extern "C" void kernel_launch(void* const* d_in, const int* in_sizes, int n_in,
                              void* d_out, int out_size)
{
    const float* x      = (const float*)d_in[0];
    const float* qkv_w  = (const float*)d_in[1];
    const float* dw_w   = (const float*)d_in[2];
    const float* proj_w = (const float*)d_in[3];
    const float* temp   = (const float*)d_in[4];
    float* out = (float*)d_out;

    float *qkv1, *qkv2, *inv, *gpart, *attn;
    __nv_bfloat16 *A1, *xs, *vs, *Wbs;
    cudaGetSymbolAddress((void**)&qkv1,  g_qkv1);
    cudaGetSymbolAddress((void**)&qkv2,  g_qkv2);
    cudaGetSymbolAddress((void**)&inv,   g_inv);
    cudaGetSymbolAddress((void**)&gpart, g_gpart);
    cudaGetSymbolAddress((void**)&attn,  g_attn);
    cudaGetSymbolAddress((void**)&A1,    g_A1);
    cudaGetSymbolAddress((void**)&xs,    g_xs);
    cudaGetSymbolAddress((void**)&vs,    g_vs);
    cudaGetSymbolAddress((void**)&Wbs,   g_Wbs);

    cudaFuncSetAttribute(gemm_split, cudaFuncAttributeMaxDynamicSharedMemorySize, GEMM_SMEM);

    // 0) operand splits
    split_w<<<(C3 * DIM + 255) / 256, 256>>>(qkv_w, A1);
    split_t<<<dim3(HWD / 32, DIM / 32, BATCH), dim3(32, 8)>>>(x, (long)DIM * HWD, xs);

    // 1) qkv = qkv_w @ x  (bf16 mma.sync, split precision)
    gemm_split<<<dim3(C3 / BM, HWD / BN, BATCH), 256, GEMM_SMEM>>>(
        A1, 0L, xs, qkv1, (long)C3 * HWD);

    // 2) depthwise 3x3
    dwconv3<<<dim3(HWD / 256, C3, BATCH), 256>>>(qkv1, dw_w, qkv2);

    // 3) norms
    rownorm<<<2 * BATCH * DIM, 256>>>(qkv2, inv);

    // 3b) split v for final GEMM
    split_t<<<dim3(HWD / 32, DIM / 32, BATCH), dim3(32, 8)>>>(
        qkv2 + (size_t)2 * DIM * HWD, (long)C3 * HWD, vs);

    // 4) Gram + scale
    gram_partial<<<dim3(8, BATCH * NH), 256>>>(qkv2, gpart);
    gram_scale<<<(64 * CH * CH + 255) / 256, 256>>>(gpart, inv, temp, attn);

    // 5) top-7 + softmax
    topk_softmax<<<BATCH * NH * CH, 64>>>(attn);

    // 6) fold proj @ blockdiag(attn) -> bf16 split
    fold_proj<<<(BATCH * DIM * DIM + 255) / 256, 256>>>(proj_w, attn, Wbs);

    // 7) out = Wb @ v  (bf16 mma.sync, split precision)
    gemm_split<<<dim3(DIM / BM, HWD / BN, BATCH), 256, GEMM_SMEM>>>(
        Wbs, (long)DIM * KP, vs, out, (long)DIM * HWD);
}

// round 5
// speedup vs baseline: 3.4636x; 1.1720x over previous
#include <cuda_runtime.h>
#include <cuda_bf16.h>
#include <math.h>
#include <stdint.h>

// ---------------------------------------------------------------------------
// Problem constants
// ---------------------------------------------------------------------------
constexpr int BATCH = 8;
constexpr int DIM   = 384;
constexpr int NH    = 8;
constexpr int CH    = 48;
constexpr int HWD   = 16384;  // 128*128
constexpr int C3    = 1152;
constexpr int TOPKN = 7;

// split-precision GEMM constants
constexpr int KP     = 1152;  // K' = 3*384 (hi*hi, lo*hi, hi*lo)
constexpr int KC     = 64;    // k per chunk (128 bytes bf16)
constexpr int NCHUNK = KP / KC;  // 18
constexpr int BM     = 128;
constexpr int BN     = 128;
constexpr int ATILE  = BM * 128;
constexpr int BTILE  = BN * 128;
constexpr int STAGE  = ATILE + BTILE;       // 32 KB
constexpr int NSTAGE = 3;
constexpr int GEMM_SMEM = NSTAGE * STAGE;   // 96 KB

constexpr int GCH = 32;        // gram chunks

// ---------------------------------------------------------------------------
// Scratch (device globals)
// ---------------------------------------------------------------------------
__device__ float g_qkv1[(size_t)BATCH * C3 * HWD];
__device__ float g_qkv2[(size_t)BATCH * C3 * HWD];
__device__ float g_inv[BATCH * 768];                    // [b][c] c<384: q, c>=384: k
__device__ float g_gpart[(size_t)GCH * BATCH * NH * CH * CH];
__device__ float g_attn[BATCH * NH * CH * CH];
__device__ __nv_bfloat16 g_A1[(size_t)C3 * KP];
__device__ __nv_bfloat16 g_xs[(size_t)BATCH * HWD * 768];
__device__ __nv_bfloat16 g_vs[(size_t)BATCH * HWD * 768];
__device__ __nv_bfloat16 g_Wbs[(size_t)BATCH * DIM * KP];

// ---------------------------------------------------------------------------
// sm_80-portable PTX helpers
// ---------------------------------------------------------------------------
__device__ __forceinline__ uint32_t smem_u32(const void* p) {
    uint32_t a;
    asm("{ .reg .u64 t; cvta.to.shared.u64 t, %1; cvt.u32.u64 %0, t; }" : "=r"(a) : "l"(p));
    return a;
}

__device__ __forceinline__ void cp16(uint32_t saddr, const void* gaddr) {
    asm volatile("cp.async.cg.shared.global [%0], [%1], 16;" :: "r"(saddr), "l"(gaddr));
}
#define CP_COMMIT() asm volatile("cp.async.commit_group;" ::: "memory")

__device__ __forceinline__ void ldmx4(uint32_t* r, uint32_t addr) {
    asm volatile("ldmatrix.sync.aligned.m8n8.x4.shared.b16 {%0,%1,%2,%3}, [%4];"
                 : "=r"(r[0]), "=r"(r[1]), "=r"(r[2]), "=r"(r[3]) : "r"(addr));
}

__device__ __forceinline__ void mma16816(float* c, const uint32_t* a, const uint32_t* b) {
    asm volatile(
        "mma.sync.aligned.m16n8k16.row.col.f32.bf16.bf16.f32 "
        "{%0,%1,%2,%3}, {%4,%5,%6,%7}, {%8,%9}, {%0,%1,%2,%3};"
        : "+f"(c[0]), "+f"(c[1]), "+f"(c[2]), "+f"(c[3])
        : "r"(a[0]), "r"(a[1]), "r"(a[2]), "r"(a[3]), "r"(b[0]), "r"(b[1]));
}

// ---------------------------------------------------------------------------
// Split-precision bf16 tensor-core GEMM (unchanged from R3)
// ---------------------------------------------------------------------------
__global__ void __launch_bounds__(256, 2)
gemm_split(const __nv_bfloat16* __restrict__ A, long aBatchStride,
           const __nv_bfloat16* __restrict__ B,
           float* __restrict__ C, long cBatchStride)
{
    extern __shared__ char sm[];
    const uint32_t smBase = smem_u32(sm);

    const int tid = threadIdx.x;
    const int wid = tid >> 5, l = tid & 31;
    const int wm = wid >> 2, wn = wid & 3;
    const int bm0 = blockIdx.x * BM;
    const int bn0 = blockIdx.y * BN;
    const int bz  = blockIdx.z;

    const __nv_bfloat16* Ab = A + (long)bz * aBatchStride + (long)bm0 * KP;
    const __nv_bfloat16* Bb = B + ((long)bz * HWD + bn0) * 768;
    float* Cb = C + (long)bz * cBatchStride + (long)bm0 * HWD + bn0;

    const int ldr = tid >> 3, ldq = tid & 7;

    auto load_chunk = [&](int c, int s) {
        const uint32_t sA = smBase + s * STAGE;
        const uint32_t sB = sA + ATILE;
        const __nv_bfloat16* ac = Ab + c * KC;
        const int bk = (c < 6) ? c * KC : c * KC - 384;
        const __nv_bfloat16* bc = Bb + bk;
#pragma unroll
        for (int i = 0; i < 4; i++) {
            int r = ldr + i * 32;
            int u = ldq ^ (r & 7);
            cp16(sA + r * 128 + u * 16, ac + (long)r * KP + ldq * 8);
        }
#pragma unroll
        for (int i = 0; i < 4; i++) {
            int r = ldr + i * 32;
            int u = ldq ^ (r & 7);
            cp16(sB + r * 128 + u * 16, bc + (long)r * 768 + ldq * 8);
        }
        CP_COMMIT();
    };

    float acc[4][4][4] = {};

    const int l7 = l & 7;
    const int a_x = l >> 4;
    const int b_x = (l >> 3) & 1;
    int arow[4], bnrow[2];
#pragma unroll
    for (int mi = 0; mi < 4; mi++)
        arow[mi] = (wm * 64 + mi * 16 + (l & 15)) * 128;
#pragma unroll
    for (int g = 0; g < 2; g++)
        bnrow[g] = (wn * 32 + g * 16 + (l >> 4) * 8 + (l & 7)) * 128;

    load_chunk(0, 0);
    load_chunk(1, 1);

    for (int c = 0; c < NCHUNK; c++) {
        if (c + 2 < NCHUNK) {
            asm volatile("cp.async.wait_group 1;" ::: "memory");
        } else {
            asm volatile("cp.async.wait_group 0;" ::: "memory");
        }
        __syncthreads();
        if (c + 2 < NCHUNK) load_chunk(c + 2, (c + 2) % NSTAGE);

        const int s = c % NSTAGE;
        const uint32_t sA = smBase + s * STAGE;
        const uint32_t sB = sA + ATILE;

#pragma unroll
        for (int kk = 0; kk < 4; kk++) {
            uint32_t afr[4][4];
#pragma unroll
            for (int mi = 0; mi < 4; mi++) {
                uint32_t u = (uint32_t)((kk * 2 + a_x) ^ l7);
                ldmx4(afr[mi], sA + arow[mi] + u * 16);
            }
            uint32_t bfr[4][2];
#pragma unroll
            for (int g = 0; g < 2; g++) {
                uint32_t t4[4];
                uint32_t u = (uint32_t)((kk * 2 + b_x) ^ l7);
                ldmx4(t4, sB + bnrow[g] + u * 16);
                bfr[2 * g][0] = t4[0]; bfr[2 * g][1] = t4[1];
                bfr[2 * g + 1][0] = t4[2]; bfr[2 * g + 1][1] = t4[3];
            }
#pragma unroll
            for (int mi = 0; mi < 4; mi++)
#pragma unroll
                for (int ni = 0; ni < 4; ni++)
                    mma16816(acc[mi][ni], afr[mi], bfr[ni]);
        }
        __syncthreads();
    }

    const int crow = l >> 2, ccol = (l & 3) * 2;
#pragma unroll
    for (int mi = 0; mi < 4; mi++) {
#pragma unroll
        for (int ni = 0; ni < 4; ni++) {
            float* p = Cb + (long)(wm * 64 + mi * 16 + crow) * HWD + wn * 32 + ni * 8 + ccol;
            *(float2*)p = make_float2(acc[mi][ni][0], acc[mi][ni][1]);
            *(float2*)(p + 8L * HWD) = make_float2(acc[mi][ni][2], acc[mi][ni][3]);
        }
    }
}

// ---------------------------------------------------------------------------
// Split qkv_w -> A' [1152][1152] bf16 = [hi | lo | hi]
// ---------------------------------------------------------------------------
__global__ void split_w(const float* __restrict__ w, __nv_bfloat16* __restrict__ o)
{
    int idx = blockIdx.x * 256 + threadIdx.x;
    if (idx >= C3 * DIM) return;
    int m = idx / DIM, k = idx % DIM;
    float v = w[idx];
    __nv_bfloat16 hi = __float2bfloat16(v);
    __nv_bfloat16 lo = __float2bfloat16(v - __bfloat162float(hi));
    o[(long)m * KP + k]       = hi;
    o[(long)m * KP + 384 + k] = lo;
    o[(long)m * KP + 768 + k] = hi;
}

// ---------------------------------------------------------------------------
// Split + transpose: src [b][384][HWD] fp32 -> dst [b][HWD][hi(384)|lo(384)] bf16
// ---------------------------------------------------------------------------
__global__ void split_t(const float* __restrict__ src, long bstride,
                        __nv_bfloat16* __restrict__ dst)
{
    __shared__ float t[32][33];
    int n0 = blockIdx.x * 32, c0 = blockIdx.y * 32, b = blockIdx.z;
    int tx = threadIdx.x, ty = threadIdx.y;
    const float* s = src + (long)b * bstride;
#pragma unroll
    for (int i = 0; i < 4; i++) {
        int cl = ty + i * 8;
        t[cl][tx] = s[(long)(c0 + cl) * HWD + n0 + tx];
    }
    __syncthreads();
    __nv_bfloat16* d = dst + (long)b * HWD * 768;
#pragma unroll
    for (int i = 0; i < 4; i++) {
        int nr = ty + i * 8;
        float v = t[tx][nr];
        __nv_bfloat16 hi = __float2bfloat16(v);
        __nv_bfloat16 lo = __float2bfloat16(v - __bfloat162float(hi));
        d[(long)(n0 + nr) * 768 + c0 + tx]       = hi;
        d[(long)(n0 + nr) * 768 + 384 + c0 + tx] = lo;
    }
}

// ---------------------------------------------------------------------------
// Depthwise 3x3 v2: one block per (b,c) plane, plane staged in smem,
// fused per-channel sum-of-squares -> inv L2 norm for q/k channels.
// ---------------------------------------------------------------------------
__global__ void __launch_bounds__(256)
dwconv3(const float* __restrict__ in, const float* __restrict__ w,
        float* __restrict__ out, float* __restrict__ inv)
{
    extern __shared__ float pl[];          // 16384 floats = 64KB
    __shared__ float red[256];

    const int c = blockIdx.x % C3;
    const int b = blockIdx.x / C3;
    const int tid = threadIdx.x;

    const float* ip = in + ((long)b * C3 + c) * HWD;
    float4* pl4 = (float4*)pl;
    const float4* ip4 = (const float4*)ip;
#pragma unroll
    for (int i = 0; i < 16; i++)
        pl4[tid + i * 256] = ip4[tid + i * 256];

    const float* wp = w + c * 9;
    float w0 = wp[0], w1 = wp[1], w2 = wp[2];
    float w3 = wp[3], w4 = wp[4], w5 = wp[5];
    float w6 = wp[6], w7 = wp[7], w8 = wp[8];
    __syncthreads();

    float* op = out + ((long)b * C3 + c) * HWD;
    float ss = 0.f;
#pragma unroll 4
    for (int i = 0; i < 64; i++) {
        int p = tid + i * 256;
        int h = p >> 7, x = p & 127;
        bool xl = x > 0, xr = x < 127;
        bool hu = h > 0, hd = h < 127;
        const float* r1 = pl + p;
        float s = w4 * r1[0];
        if (xl) s += w3 * r1[-1];
        if (xr) s += w5 * r1[1];
        if (hu) {
            const float* r0 = r1 - 128;
            s += w1 * r0[0];
            if (xl) s += w0 * r0[-1];
            if (xr) s += w2 * r0[1];
        }
        if (hd) {
            const float* r2 = r1 + 128;
            s += w7 * r2[0];
            if (xl) s += w6 * r2[-1];
            if (xr) s += w8 * r2[1];
        }
        op[p] = s;
        ss += s * s;
    }

    if (c < 768) {
        red[tid] = ss;
        __syncthreads();
        for (int st = 128; st > 0; st >>= 1) {
            if (tid < st) red[tid] += red[tid + st];
            __syncthreads();
        }
        if (tid == 0) {
            float n = sqrtf(red[0]);
            inv[b * 768 + c] = 1.f / fmaxf(n, 1e-12f);
        }
    }
}

// ---------------------------------------------------------------------------
// Gram partial v2: 32 chunks x 64 (b,h); float4 loads; t-major smem
// ---------------------------------------------------------------------------
__global__ void __launch_bounds__(256)
gram_partial(const float* __restrict__ qkv2, float* __restrict__ gpart)
{
    const int chunk = blockIdx.x;         // 0..31 (512 cols each)
    const int bh = blockIdx.y;            // 0..63
    const int b = bh >> 3, h = bh & 7;
    const float* qb = qkv2 + ((long)b * C3 + h * CH) * HWD;
    const float* kb = qb + (long)DIM * HWD;

    __shared__ float qs[64][49], ks[64][49];
    const int tid = threadIdx.x;
    const int tx = tid & 15, ty = tid >> 4;
    float acc[3][3] = {};

    const int n0 = chunk * 512;
    for (int slab = 0; slab < 8; slab++) {
        const int base = n0 + slab * 64;
        __syncthreads();
#pragma unroll
        for (int j = 0; j < 3; j++) {
            int id = tid + j * 256;       // 0..767
            int rid = id >> 4, c4 = id & 15;
            float4 v = *(const float4*)(qb + (long)rid * HWD + base + c4 * 4);
            qs[c4 * 4 + 0][rid] = v.x; qs[c4 * 4 + 1][rid] = v.y;
            qs[c4 * 4 + 2][rid] = v.z; qs[c4 * 4 + 3][rid] = v.w;
            float4 u = *(const float4*)(kb + (long)rid * HWD + base + c4 * 4);
            ks[c4 * 4 + 0][rid] = u.x; ks[c4 * 4 + 1][rid] = u.y;
            ks[c4 * 4 + 2][rid] = u.z; ks[c4 * 4 + 3][rid] = u.w;
        }
        __syncthreads();
#pragma unroll 8
        for (int t = 0; t < 64; t++) {
            float qa[3], ka[3];
#pragma unroll
            for (int i = 0; i < 3; i++) qa[i] = qs[t][ty * 3 + i];
#pragma unroll
            for (int j = 0; j < 3; j++) ka[j] = ks[t][tx * 3 + j];
#pragma unroll
            for (int i = 0; i < 3; i++)
#pragma unroll
                for (int j = 0; j < 3; j++)
                    acc[i][j] += qa[i] * ka[j];
        }
    }
    float* op = gpart + ((long)chunk * 64 + bh) * (CH * CH);
#pragma unroll
    for (int i = 0; i < 3; i++)
#pragma unroll
        for (int j = 0; j < 3; j++)
            op[(ty * 3 + i) * CH + tx * 3 + j] = acc[i][j];
}

__global__ void gram_scale(const float* __restrict__ gpart, const float* __restrict__ inv,
                           const float* __restrict__ temp, float* __restrict__ attn)
{
    int idx = blockIdx.x * 256 + threadIdx.x;
    if (idx >= 64 * CH * CH) return;
    int bh = idx / (CH * CH), r = idx % (CH * CH);
    int c = r / CH, d = r % CH;
    int b = bh >> 3, h = bh & 7;
    float s = 0.f;
#pragma unroll
    for (int ck = 0; ck < GCH; ck++) s += gpart[((long)ck * 64 + bh) * (CH * CH) + r];
    float iq = inv[b * 768 + h * CH + c];
    float ik = inv[b * 768 + 384 + h * CH + d];
    attn[idx] = s * iq * ik * temp[h];
}

__global__ void topk_softmax(float* __restrict__ attn)
{
    int row = blockIdx.x;
    float* p = attn + (long)row * CH;
    __shared__ float s[CH], e[CH];
    int i = threadIdx.x;
    if (i < CH) s[i] = p[i];
    __syncthreads();
    if (i < CH) {
        float v = s[i];
        int cnt = 0;
        float m = -1e30f;
#pragma unroll
        for (int j = 0; j < CH; j++) {
            cnt += (s[j] > v);
            m = fmaxf(m, s[j]);
        }
        e[i] = (cnt < TOPKN) ? expf(v - m) : 0.f;
    }
    __syncthreads();
    if (i < CH) {
        float sum = 0.f;
#pragma unroll
        for (int j = 0; j < CH; j++) sum += e[j];
        p[i] = e[i] / sum;
    }
}

// ---------------------------------------------------------------------------
// Fold proj_w @ blockdiag(attn) -> Wbs (bf16 split [hi|lo|hi])
// ---------------------------------------------------------------------------
__global__ void fold_proj(const float* __restrict__ projw, const float* __restrict__ attn,
                          __nv_bfloat16* __restrict__ Wbs)
{
    int idx = blockIdx.x * 256 + threadIdx.x;
    if (idx >= BATCH * DIM * DIM) return;
    int b = idx / (DIM * DIM);
    int r = idx % (DIM * DIM);
    int o = r / DIM, dg = r % DIM;
    int h = dg / CH, d = dg % CH;
    const float* pw = projw + o * DIM + h * CH;
    const float* at = attn + ((long)(b * NH + h) * CH) * CH + d;
    float s = 0.f;
#pragma unroll
    for (int c = 0; c < CH; c++) s += pw[c] * at[c * CH];
    __nv_bfloat16 hi = __float2bfloat16(s);
    __nv_bfloat16 lo = __float2bfloat16(s - __bfloat162float(hi));
    __nv_bfloat16* row = Wbs + ((long)b * DIM + o) * KP;
    row[dg]       = hi;
    row[384 + dg] = lo;
    row[768 + dg] = hi;
}

// ---------------------------------------------------------------------------
extern "C" void kernel_launch(void* const* d_in, const int* in_sizes, int n_in,
                              void* d_out, int out_size)
{
    const float* x      = (const float*)d_in[0];
    const float* qkv_w  = (const float*)d_in[1];
    const float* dw_w   = (const float*)d_in[2];
    const float* proj_w = (const float*)d_in[3];
    const float* temp   = (const float*)d_in[4];
    float* out = (float*)d_out;

    float *qkv1, *qkv2, *inv, *gpart, *attn;
    __nv_bfloat16 *A1, *xs, *vs, *Wbs;
    cudaGetSymbolAddress((void**)&qkv1,  g_qkv1);
    cudaGetSymbolAddress((void**)&qkv2,  g_qkv2);
    cudaGetSymbolAddress((void**)&inv,   g_inv);
    cudaGetSymbolAddress((void**)&gpart, g_gpart);
    cudaGetSymbolAddress((void**)&attn,  g_attn);
    cudaGetSymbolAddress((void**)&A1,    g_A1);
    cudaGetSymbolAddress((void**)&xs,    g_xs);
    cudaGetSymbolAddress((void**)&vs,    g_vs);
    cudaGetSymbolAddress((void**)&Wbs,   g_Wbs);

    cudaFuncSetAttribute(gemm_split, cudaFuncAttributeMaxDynamicSharedMemorySize, GEMM_SMEM);
    cudaFuncSetAttribute(dwconv3, cudaFuncAttributeMaxDynamicSharedMemorySize, 65536);

    // 0) operand splits
    split_w<<<(C3 * DIM + 255) / 256, 256>>>(qkv_w, A1);
    split_t<<<dim3(HWD / 32, DIM / 32, BATCH), dim3(32, 8)>>>(x, (long)DIM * HWD, xs);

    // 1) qkv = qkv_w @ x  (bf16 mma.sync, split precision)
    gemm_split<<<dim3(C3 / BM, HWD / BN, BATCH), 256, GEMM_SMEM>>>(
        A1, 0L, xs, qkv1, (long)C3 * HWD);

    // 2) depthwise 3x3 + fused channel norms
    dwconv3<<<BATCH * C3, 256, 65536>>>(qkv1, dw_w, qkv2, inv);

    // 3) split v for final GEMM
    split_t<<<dim3(HWD / 32, DIM / 32, BATCH), dim3(32, 8)>>>(
        qkv2 + (size_t)2 * DIM * HWD, (long)C3 * HWD, vs);

    // 4) Gram + scale
    gram_partial<<<dim3(GCH, BATCH * NH), 256>>>(qkv2, gpart);
    gram_scale<<<(64 * CH * CH + 255) / 256, 256>>>(gpart, inv, temp, attn);

    // 5) top-7 + softmax
    topk_softmax<<<BATCH * NH * CH, 64>>>(attn);

    // 6) fold proj @ blockdiag(attn) -> bf16 split
    fold_proj<<<(BATCH * DIM * DIM + 255) / 256, 256>>>(proj_w, attn, Wbs);

    // 7) out = Wb @ v  (bf16 mma.sync, split precision)
    gemm_split<<<dim3(DIM / BM, HWD / BN, BATCH), 256, GEMM_SMEM>>>(
        Wbs, (long)DIM * KP, vs, out, (long)DIM * HWD);
}

// round 6
// speedup vs baseline: 3.8866x; 1.1221x over previous
#include <cuda_runtime.h>
#include <cuda_bf16.h>
#include <math.h>
#include <stdint.h>

// ---------------------------------------------------------------------------
// Problem constants
// ---------------------------------------------------------------------------
constexpr int BATCH = 8;
constexpr int DIM   = 384;
constexpr int NH    = 8;
constexpr int CH    = 48;
constexpr int HWD   = 16384;  // 128*128
constexpr int C3    = 1152;
constexpr int TOPKN = 7;

// split-precision GEMM constants
constexpr int KP     = 1152;
constexpr int KC     = 64;
constexpr int NCHUNK = KP / KC;  // 18
constexpr int BM     = 128;
constexpr int BN     = 128;
constexpr int ATILE  = BM * 128;
constexpr int BTILE  = BN * 128;
constexpr int STAGE  = ATILE + BTILE;       // 32 KB
constexpr int NSTAGE = 3;
constexpr int GEMM_SMEM = NSTAGE * STAGE;   // 96 KB

constexpr int GCH = 32;        // gram chunks

// dwconv strips
constexpr int SROWS = 32;                 // output rows per block
constexpr int NSTRIP = 128 / SROWS;       // 4
constexpr int SPITCH = 130;               // smem row pitch (1 zero col each side)

// ---------------------------------------------------------------------------
// Scratch (device globals)
// ---------------------------------------------------------------------------
__device__ float g_qkv1[(size_t)BATCH * C3 * HWD];
__device__ float g_qkv2[(size_t)BATCH * C3 * HWD];
__device__ float g_ssp[BATCH * 768 * NSTRIP];           // partial sum-of-squares
__device__ float g_inv[BATCH * 768];                    // [b][c] c<384: q, c>=384: k
__device__ float g_gpart[(size_t)GCH * BATCH * NH * CH * CH];
__device__ float g_attn[BATCH * NH * CH * CH];
__device__ __nv_bfloat16 g_A1[(size_t)C3 * KP];
__device__ __nv_bfloat16 g_xs[(size_t)BATCH * HWD * 768];
__device__ __nv_bfloat16 g_vs[(size_t)BATCH * HWD * 768];
__device__ __nv_bfloat16 g_Wbs[(size_t)BATCH * DIM * KP];

// ---------------------------------------------------------------------------
// sm_80-portable PTX helpers
// ---------------------------------------------------------------------------
__device__ __forceinline__ uint32_t smem_u32(const void* p) {
    uint32_t a;
    asm("{ .reg .u64 t; cvta.to.shared.u64 t, %1; cvt.u32.u64 %0, t; }" : "=r"(a) : "l"(p));
    return a;
}

__device__ __forceinline__ void cp16(uint32_t saddr, const void* gaddr) {
    asm volatile("cp.async.cg.shared.global [%0], [%1], 16;" :: "r"(saddr), "l"(gaddr));
}
#define CP_COMMIT() asm volatile("cp.async.commit_group;" ::: "memory")

__device__ __forceinline__ void ldmx4(uint32_t* r, uint32_t addr) {
    asm volatile("ldmatrix.sync.aligned.m8n8.x4.shared.b16 {%0,%1,%2,%3}, [%4];"
                 : "=r"(r[0]), "=r"(r[1]), "=r"(r[2]), "=r"(r[3]) : "r"(addr));
}

__device__ __forceinline__ void mma16816(float* c, const uint32_t* a, const uint32_t* b) {
    asm volatile(
        "mma.sync.aligned.m16n8k16.row.col.f32.bf16.bf16.f32 "
        "{%0,%1,%2,%3}, {%4,%5,%6,%7}, {%8,%9}, {%0,%1,%2,%3};"
        : "+f"(c[0]), "+f"(c[1]), "+f"(c[2]), "+f"(c[3])
        : "r"(a[0]), "r"(a[1]), "r"(a[2]), "r"(a[3]), "r"(b[0]), "r"(b[1]));
}

// ---------------------------------------------------------------------------
// Split-precision bf16 tensor-core GEMM (unchanged)
// ---------------------------------------------------------------------------
__global__ void __launch_bounds__(256, 2)
gemm_split(const __nv_bfloat16* __restrict__ A, long aBatchStride,
           const __nv_bfloat16* __restrict__ B,
           float* __restrict__ C, long cBatchStride)
{
    extern __shared__ char sm[];
    const uint32_t smBase = smem_u32(sm);

    const int tid = threadIdx.x;
    const int wid = tid >> 5, l = tid & 31;
    const int wm = wid >> 2, wn = wid & 3;
    const int bm0 = blockIdx.x * BM;
    const int bn0 = blockIdx.y * BN;
    const int bz  = blockIdx.z;

    const __nv_bfloat16* Ab = A + (long)bz * aBatchStride + (long)bm0 * KP;
    const __nv_bfloat16* Bb = B + ((long)bz * HWD + bn0) * 768;
    float* Cb = C + (long)bz * cBatchStride + (long)bm0 * HWD + bn0;

    const int ldr = tid >> 3, ldq = tid & 7;

    auto load_chunk = [&](int c, int s) {
        const uint32_t sA = smBase + s * STAGE;
        const uint32_t sB = sA + ATILE;
        const __nv_bfloat16* ac = Ab + c * KC;
        const int bk = (c < 6) ? c * KC : c * KC - 384;
        const __nv_bfloat16* bc = Bb + bk;
#pragma unroll
        for (int i = 0; i < 4; i++) {
            int r = ldr + i * 32;
            int u = ldq ^ (r & 7);
            cp16(sA + r * 128 + u * 16, ac + (long)r * KP + ldq * 8);
        }
#pragma unroll
        for (int i = 0; i < 4; i++) {
            int r = ldr + i * 32;
            int u = ldq ^ (r & 7);
            cp16(sB + r * 128 + u * 16, bc + (long)r * 768 + ldq * 8);
        }
        CP_COMMIT();
    };

    float acc[4][4][4] = {};

    const int l7 = l & 7;
    const int a_x = l >> 4;
    const int b_x = (l >> 3) & 1;
    int arow[4], bnrow[2];
#pragma unroll
    for (int mi = 0; mi < 4; mi++)
        arow[mi] = (wm * 64 + mi * 16 + (l & 15)) * 128;
#pragma unroll
    for (int g = 0; g < 2; g++)
        bnrow[g] = (wn * 32 + g * 16 + (l >> 4) * 8 + (l & 7)) * 128;

    load_chunk(0, 0);
    load_chunk(1, 1);

    for (int c = 0; c < NCHUNK; c++) {
        if (c + 2 < NCHUNK) {
            asm volatile("cp.async.wait_group 1;" ::: "memory");
        } else {
            asm volatile("cp.async.wait_group 0;" ::: "memory");
        }
        __syncthreads();
        if (c + 2 < NCHUNK) load_chunk(c + 2, (c + 2) % NSTAGE);

        const int s = c % NSTAGE;
        const uint32_t sA = smBase + s * STAGE;
        const uint32_t sB = sA + ATILE;

#pragma unroll
        for (int kk = 0; kk < 4; kk++) {
            uint32_t afr[4][4];
#pragma unroll
            for (int mi = 0; mi < 4; mi++) {
                uint32_t u = (uint32_t)((kk * 2 + a_x) ^ l7);
                ldmx4(afr[mi], sA + arow[mi] + u * 16);
            }
            uint32_t bfr[4][2];
#pragma unroll
            for (int g = 0; g < 2; g++) {
                uint32_t t4[4];
                uint32_t u = (uint32_t)((kk * 2 + b_x) ^ l7);
                ldmx4(t4, sB + bnrow[g] + u * 16);
                bfr[2 * g][0] = t4[0]; bfr[2 * g][1] = t4[1];
                bfr[2 * g + 1][0] = t4[2]; bfr[2 * g + 1][1] = t4[3];
            }
#pragma unroll
            for (int mi = 0; mi < 4; mi++)
#pragma unroll
                for (int ni = 0; ni < 4; ni++)
                    mma16816(acc[mi][ni], afr[mi], bfr[ni]);
        }
        __syncthreads();
    }

    const int crow = l >> 2, ccol = (l & 3) * 2;
#pragma unroll
    for (int mi = 0; mi < 4; mi++) {
#pragma unroll
        for (int ni = 0; ni < 4; ni++) {
            float* p = Cb + (long)(wm * 64 + mi * 16 + crow) * HWD + wn * 32 + ni * 8 + ccol;
            *(float2*)p = make_float2(acc[mi][ni][0], acc[mi][ni][1]);
            *(float2*)(p + 8L * HWD) = make_float2(acc[mi][ni][2], acc[mi][ni][3]);
        }
    }
}

// ---------------------------------------------------------------------------
// Split qkv_w -> A' [1152][1152] bf16 = [hi | lo | hi]
// ---------------------------------------------------------------------------
__global__ void split_w(const float* __restrict__ w, __nv_bfloat16* __restrict__ o)
{
    int idx = blockIdx.x * 256 + threadIdx.x;
    if (idx >= C3 * DIM) return;
    int m = idx / DIM, k = idx % DIM;
    float v = w[idx];
    __nv_bfloat16 hi = __float2bfloat16(v);
    __nv_bfloat16 lo = __float2bfloat16(v - __bfloat162float(hi));
    o[(long)m * KP + k]       = hi;
    o[(long)m * KP + 384 + k] = lo;
    o[(long)m * KP + 768 + k] = hi;
}

// ---------------------------------------------------------------------------
// Split + transpose: src [b][384][HWD] fp32 -> dst [b][HWD][hi|lo] bf16
// ---------------------------------------------------------------------------
__global__ void split_t(const float* __restrict__ src, long bstride,
                        __nv_bfloat16* __restrict__ dst)
{
    __shared__ float t[32][33];
    int n0 = blockIdx.x * 32, c0 = blockIdx.y * 32, b = blockIdx.z;
    int tx = threadIdx.x, ty = threadIdx.y;
    const float* s = src + (long)b * bstride;
#pragma unroll
    for (int i = 0; i < 4; i++) {
        int cl = ty + i * 8;
        t[cl][tx] = s[(long)(c0 + cl) * HWD + n0 + tx];
    }
    __syncthreads();
    __nv_bfloat16* d = dst + (long)b * HWD * 768;
#pragma unroll
    for (int i = 0; i < 4; i++) {
        int nr = ty + i * 8;
        float v = t[tx][nr];
        __nv_bfloat16 hi = __float2bfloat16(v);
        __nv_bfloat16 lo = __float2bfloat16(v - __bfloat162float(hi));
        d[(long)(n0 + nr) * 768 + c0 + tx]       = hi;
        d[(long)(n0 + nr) * 768 + 384 + c0 + tx] = lo;
    }
}

// ---------------------------------------------------------------------------
// Depthwise 3x3 v3: strip-tiled (32 rows + halo), zero-padded smem, branchless
// inner loop; per-strip partial sum-of-squares for fused norms.
// ---------------------------------------------------------------------------
__global__ void __launch_bounds__(256)
dwconv3(const float* __restrict__ in, const float* __restrict__ w,
        float* __restrict__ out, float* __restrict__ ssp)
{
    __shared__ float pl[(SROWS + 2) * SPITCH];   // 34 x 130 = 17.3KB
    __shared__ float red[256];

    const int strip = blockIdx.x & (NSTRIP - 1);
    const int c = (blockIdx.x >> 2) % C3;
    const int b = blockIdx.x / (NSTRIP * C3);
    const int tid = threadIdx.x;

    // zero full smem tile (covers halo rows at image edges + side cols)
#pragma unroll
    for (int i = tid; i < (SROWS + 2) * SPITCH; i += 256)
        pl[i] = 0.f;
    __syncthreads();

    const int r0 = strip * SROWS;                 // first output row
    const float* ip = in + ((long)b * C3 + c) * HWD;

    // load rows [r0-1, r0+SROWS] (clip) into smem rows [0, 33], col offset 1
    {
        const int rlo = (strip == 0) ? 1 : 0;                 // smem row bounds
        const int rhi = (strip == NSTRIP - 1) ? SROWS : SROWS + 1;
        for (int i = tid; i < (rhi - rlo + 1) * 128; i += 256) {
            int lr = rlo + (i >> 7);
            int x = i & 127;
            pl[lr * SPITCH + 1 + x] = ip[(long)(r0 - 1 + lr) * 128 + x];
        }
    }

    const float* wp = w + c * 9;
    float w0 = wp[0], w1 = wp[1], w2 = wp[2];
    float w3 = wp[3], w4 = wp[4], w5 = wp[5];
    float w6 = wp[6], w7 = wp[7], w8 = wp[8];
    __syncthreads();

    float* op = out + ((long)b * C3 + c) * HWD + (long)r0 * 128;
    float ss = 0.f;
#pragma unroll
    for (int i = 0; i < 16; i++) {
        int p = tid + i * 256;                    // 0..4095
        int h = p >> 7, x = p & 127;
        const float* r1 = pl + (h + 1) * SPITCH + 1 + x;
        const float* rA = r1 - SPITCH;
        const float* rB = r1 + SPITCH;
        float s = w0 * rA[-1] + w1 * rA[0] + w2 * rA[1]
                + w3 * r1[-1] + w4 * r1[0] + w5 * r1[1]
                + w6 * rB[-1] + w7 * rB[0] + w8 * rB[1];
        op[p] = s;
        ss += s * s;
    }

    if (c < 768) {
        red[tid] = ss;
        __syncthreads();
        for (int st = 128; st > 0; st >>= 1) {
            if (tid < st) red[tid] += red[tid + st];
            __syncthreads();
        }
        if (tid == 0)
            ssp[(b * 768 + c) * NSTRIP + strip] = red[0];
    }
}

// finalize inv norms from strip partials
__global__ void norm_fin(const float* __restrict__ ssp, float* __restrict__ inv)
{
    int i = blockIdx.x * 256 + threadIdx.x;
    if (i >= BATCH * 768) return;
    float s = 0.f;
#pragma unroll
    for (int j = 0; j < NSTRIP; j++) s += ssp[i * NSTRIP + j];
    inv[i] = 1.f / fmaxf(sqrtf(s), 1e-12f);
}

// ---------------------------------------------------------------------------
// Gram partial (unchanged from R4)
// ---------------------------------------------------------------------------
__global__ void __launch_bounds__(256)
gram_partial(const float* __restrict__ qkv2, float* __restrict__ gpart)
{
    const int chunk = blockIdx.x;
    const int bh = blockIdx.y;
    const int b = bh >> 3, h = bh & 7;
    const float* qb = qkv2 + ((long)b * C3 + h * CH) * HWD;
    const float* kb = qb + (long)DIM * HWD;

    __shared__ float qs[64][49], ks[64][49];
    const int tid = threadIdx.x;
    const int tx = tid & 15, ty = tid >> 4;
    float acc[3][3] = {};

    const int n0 = chunk * 512;
    for (int slab = 0; slab < 8; slab++) {
        const int base = n0 + slab * 64;
        __syncthreads();
#pragma unroll
        for (int j = 0; j < 3; j++) {
            int id = tid + j * 256;
            int rid = id >> 4, c4 = id & 15;
            float4 v = *(const float4*)(qb + (long)rid * HWD + base + c4 * 4);
            qs[c4 * 4 + 0][rid] = v.x; qs[c4 * 4 + 1][rid] = v.y;
            qs[c4 * 4 + 2][rid] = v.z; qs[c4 * 4 + 3][rid] = v.w;
            float4 u = *(const float4*)(kb + (long)rid * HWD + base + c4 * 4);
            ks[c4 * 4 + 0][rid] = u.x; ks[c4 * 4 + 1][rid] = u.y;
            ks[c4 * 4 + 2][rid] = u.z; ks[c4 * 4 + 3][rid] = u.w;
        }
        __syncthreads();
#pragma unroll 8
        for (int t = 0; t < 64; t++) {
            float qa[3], ka[3];
#pragma unroll
            for (int i = 0; i < 3; i++) qa[i] = qs[t][ty * 3 + i];
#pragma unroll
            for (int j = 0; j < 3; j++) ka[j] = ks[t][tx * 3 + j];
#pragma unroll
            for (int i = 0; i < 3; i++)
#pragma unroll
                for (int j = 0; j < 3; j++)
                    acc[i][j] += qa[i] * ka[j];
        }
    }
    float* op = gpart + ((long)chunk * 64 + bh) * (CH * CH);
#pragma unroll
    for (int i = 0; i < 3; i++)
#pragma unroll
        for (int j = 0; j < 3; j++)
            op[(ty * 3 + i) * CH + tx * 3 + j] = acc[i][j];
}

__global__ void gram_scale(const float* __restrict__ gpart, const float* __restrict__ inv,
                           const float* __restrict__ temp, float* __restrict__ attn)
{
    int idx = blockIdx.x * 256 + threadIdx.x;
    if (idx >= 64 * CH * CH) return;
    int bh = idx / (CH * CH), r = idx % (CH * CH);
    int c = r / CH, d = r % CH;
    int b = bh >> 3, h = bh & 7;
    float s = 0.f;
#pragma unroll
    for (int ck = 0; ck < GCH; ck++) s += gpart[((long)ck * 64 + bh) * (CH * CH) + r];
    float iq = inv[b * 768 + h * CH + c];
    float ik = inv[b * 768 + 384 + h * CH + d];
    attn[idx] = s * iq * ik * temp[h];
}

__global__ void topk_softmax(float* __restrict__ attn)
{
    int row = blockIdx.x;
    float* p = attn + (long)row * CH;
    __shared__ float s[CH], e[CH];
    int i = threadIdx.x;
    if (i < CH) s[i] = p[i];
    __syncthreads();
    if (i < CH) {
        float v = s[i];
        int cnt = 0;
        float m = -1e30f;
#pragma unroll
        for (int j = 0; j < CH; j++) {
            cnt += (s[j] > v);
            m = fmaxf(m, s[j]);
        }
        e[i] = (cnt < TOPKN) ? expf(v - m) : 0.f;
    }
    __syncthreads();
    if (i < CH) {
        float sum = 0.f;
#pragma unroll
        for (int j = 0; j < CH; j++) sum += e[j];
        p[i] = e[i] / sum;
    }
}

// ---------------------------------------------------------------------------
// Fold proj_w @ blockdiag(attn) -> Wbs (bf16 split [hi|lo|hi])
// ---------------------------------------------------------------------------
__global__ void fold_proj(const float* __restrict__ projw, const float* __restrict__ attn,
                          __nv_bfloat16* __restrict__ Wbs)
{
    int idx = blockIdx.x * 256 + threadIdx.x;
    if (idx >= BATCH * DIM * DIM) return;
    int b = idx / (DIM * DIM);
    int r = idx % (DIM * DIM);
    int o = r / DIM, dg = r % DIM;
    int h = dg / CH, d = dg % CH;
    const float* pw = projw + o * DIM + h * CH;
    const float* at = attn + ((long)(b * NH + h) * CH) * CH + d;
    float s = 0.f;
#pragma unroll
    for (int c = 0; c < CH; c++) s += pw[c] * at[c * CH];
    __nv_bfloat16 hi = __float2bfloat16(s);
    __nv_bfloat16 lo = __float2bfloat16(s - __bfloat162float(hi));
    __nv_bfloat16* row = Wbs + ((long)b * DIM + o) * KP;
    row[dg]       = hi;
    row[384 + dg] = lo;
    row[768 + dg] = hi;
}

// ---------------------------------------------------------------------------
extern "C" void kernel_launch(void* const* d_in, const int* in_sizes, int n_in,
                              void* d_out, int out_size)
{
    const float* x      = (const float*)d_in[0];
    const float* qkv_w  = (const float*)d_in[1];
    const float* dw_w   = (const float*)d_in[2];
    const float* proj_w = (const float*)d_in[3];
    const float* temp   = (const float*)d_in[4];
    float* out = (float*)d_out;

    float *qkv1, *qkv2, *ssp, *inv, *gpart, *attn;
    __nv_bfloat16 *A1, *xs, *vs, *Wbs;
    cudaGetSymbolAddress((void**)&qkv1,  g_qkv1);
    cudaGetSymbolAddress((void**)&qkv2,  g_qkv2);
    cudaGetSymbolAddress((void**)&ssp,   g_ssp);
    cudaGetSymbolAddress((void**)&inv,   g_inv);
    cudaGetSymbolAddress((void**)&gpart, g_gpart);
    cudaGetSymbolAddress((void**)&attn,  g_attn);
    cudaGetSymbolAddress((void**)&A1,    g_A1);
    cudaGetSymbolAddress((void**)&xs,    g_xs);
    cudaGetSymbolAddress((void**)&vs,    g_vs);
    cudaGetSymbolAddress((void**)&Wbs,   g_Wbs);

    cudaFuncSetAttribute(gemm_split, cudaFuncAttributeMaxDynamicSharedMemorySize, GEMM_SMEM);

    // 0) operand splits
    split_w<<<(C3 * DIM + 255) / 256, 256>>>(qkv_w, A1);
    split_t<<<dim3(HWD / 32, DIM / 32, BATCH), dim3(32, 8)>>>(x, (long)DIM * HWD, xs);

    // 1) qkv = qkv_w @ x  (bf16 mma.sync, split precision)
    gemm_split<<<dim3(C3 / BM, HWD / BN, BATCH), 256, GEMM_SMEM>>>(
        A1, 0L, xs, qkv1, (long)C3 * HWD);

    // 2) depthwise 3x3 (strip-tiled) + partial norms, then finalize
    dwconv3<<<BATCH * C3 * NSTRIP, 256>>>(qkv1, dw_w, qkv2, ssp);
    norm_fin<<<(BATCH * 768 + 255) / 256, 256>>>(ssp, inv);

    // 3) split v for final GEMM
    split_t<<<dim3(HWD / 32, DIM / 32, BATCH), dim3(32, 8)>>>(
        qkv2 + (size_t)2 * DIM * HWD, (long)C3 * HWD, vs);

    // 4) Gram + scale
    gram_partial<<<dim3(GCH, BATCH * NH), 256>>>(qkv2, gpart);
    gram_scale<<<(64 * CH * CH + 255) / 256, 256>>>(gpart, inv, temp, attn);

    // 5) top-7 + softmax
    topk_softmax<<<BATCH * NH * CH, 64>>>(attn);

    // 6) fold proj @ blockdiag(attn) -> bf16 split
    fold_proj<<<(BATCH * DIM * DIM + 255) / 256, 256>>>(proj_w, attn, Wbs);

    // 7) out = Wb @ v  (bf16 mma.sync, split precision)
    gemm_split<<<dim3(DIM / BM, HWD / BN, BATCH), 256, GEMM_SMEM>>>(
        Wbs, (long)DIM * KP, vs, out, (long)DIM * HWD);
}

// round 7
// speedup vs baseline: 3.9408x; 1.0139x over previous
#include <cuda_runtime.h>
#include <cuda_bf16.h>
#include <math.h>
#include <stdint.h>

// ---------------------------------------------------------------------------
// Problem constants
// ---------------------------------------------------------------------------
constexpr int BATCH = 8;
constexpr int DIM   = 384;
constexpr int NH    = 8;
constexpr int CH    = 48;
constexpr int HWD   = 16384;  // 128*128
constexpr int C3    = 1152;
constexpr int TOPKN = 7;

// split-precision GEMM constants
constexpr int KP     = 1152;
constexpr int KC     = 64;
constexpr int NCHUNK = KP / KC;  // 18
constexpr int BM     = 128;
constexpr int BN     = 128;
constexpr int ATILE  = BM * 128;
constexpr int BTILE  = BN * 128;
constexpr int STAGE  = ATILE + BTILE;       // 32 KB
constexpr int NSTAGE = 3;
constexpr int GEMM_SMEM = NSTAGE * STAGE;   // 96 KB

constexpr int GCH = 32;        // gram chunks

// dwconv strips
constexpr int SROWS = 32;                 // output rows per block
constexpr int NSTRIP = 128 / SROWS;       // 4
constexpr int SPITCH = 136;               // smem row pitch (4 zero cols each side)

// ---------------------------------------------------------------------------
// Scratch (device globals)
// ---------------------------------------------------------------------------
__device__ float g_qkv1[(size_t)BATCH * C3 * HWD];
__device__ float g_qkv2[(size_t)BATCH * C3 * HWD];
__device__ float g_ssp[BATCH * 768 * NSTRIP];           // partial sum-of-squares
__device__ float g_inv[BATCH * 768];                    // [b][c] c<384: q, c>=384: k
__device__ float g_gpart[(size_t)GCH * BATCH * NH * CH * CH];
__device__ float g_attn[BATCH * NH * CH * CH];
__device__ __nv_bfloat16 g_A1[(size_t)C3 * KP];
__device__ __nv_bfloat16 g_xs[(size_t)BATCH * HWD * 768];
__device__ __nv_bfloat16 g_vs[(size_t)BATCH * HWD * 768];
__device__ __nv_bfloat16 g_Wbs[(size_t)BATCH * DIM * KP];

// ---------------------------------------------------------------------------
// sm_80-portable PTX helpers
// ---------------------------------------------------------------------------
__device__ __forceinline__ uint32_t smem_u32(const void* p) {
    uint32_t a;
    asm("{ .reg .u64 t; cvta.to.shared.u64 t, %1; cvt.u32.u64 %0, t; }" : "=r"(a) : "l"(p));
    return a;
}

__device__ __forceinline__ void cp16(uint32_t saddr, const void* gaddr) {
    asm volatile("cp.async.cg.shared.global [%0], [%1], 16;" :: "r"(saddr), "l"(gaddr));
}
#define CP_COMMIT() asm volatile("cp.async.commit_group;" ::: "memory")

__device__ __forceinline__ void ldmx4(uint32_t* r, uint32_t addr) {
    asm volatile("ldmatrix.sync.aligned.m8n8.x4.shared.b16 {%0,%1,%2,%3}, [%4];"
                 : "=r"(r[0]), "=r"(r[1]), "=r"(r[2]), "=r"(r[3]) : "r"(addr));
}

__device__ __forceinline__ void mma16816(float* c, const uint32_t* a, const uint32_t* b) {
    asm volatile(
        "mma.sync.aligned.m16n8k16.row.col.f32.bf16.bf16.f32 "
        "{%0,%1,%2,%3}, {%4,%5,%6,%7}, {%8,%9}, {%0,%1,%2,%3};"
        : "+f"(c[0]), "+f"(c[1]), "+f"(c[2]), "+f"(c[3])
        : "r"(a[0]), "r"(a[1]), "r"(a[2]), "r"(a[3]), "r"(b[0]), "r"(b[1]));
}

// ---------------------------------------------------------------------------
// Split-precision bf16 tensor-core GEMM (unchanged)
// ---------------------------------------------------------------------------
__global__ void __launch_bounds__(256, 2)
gemm_split(const __nv_bfloat16* __restrict__ A, long aBatchStride,
           const __nv_bfloat16* __restrict__ B,
           float* __restrict__ C, long cBatchStride)
{
    extern __shared__ char sm[];
    const uint32_t smBase = smem_u32(sm);

    const int tid = threadIdx.x;
    const int wid = tid >> 5, l = tid & 31;
    const int wm = wid >> 2, wn = wid & 3;
    const int bm0 = blockIdx.x * BM;
    const int bn0 = blockIdx.y * BN;
    const int bz  = blockIdx.z;

    const __nv_bfloat16* Ab = A + (long)bz * aBatchStride + (long)bm0 * KP;
    const __nv_bfloat16* Bb = B + ((long)bz * HWD + bn0) * 768;
    float* Cb = C + (long)bz * cBatchStride + (long)bm0 * HWD + bn0;

    const int ldr = tid >> 3, ldq = tid & 7;

    auto load_chunk = [&](int c, int s) {
        const uint32_t sA = smBase + s * STAGE;
        const uint32_t sB = sA + ATILE;
        const __nv_bfloat16* ac = Ab + c * KC;
        const int bk = (c < 6) ? c * KC : c * KC - 384;
        const __nv_bfloat16* bc = Bb + bk;
#pragma unroll
        for (int i = 0; i < 4; i++) {
            int r = ldr + i * 32;
            int u = ldq ^ (r & 7);
            cp16(sA + r * 128 + u * 16, ac + (long)r * KP + ldq * 8);
        }
#pragma unroll
        for (int i = 0; i < 4; i++) {
            int r = ldr + i * 32;
            int u = ldq ^ (r & 7);
            cp16(sB + r * 128 + u * 16, bc + (long)r * 768 + ldq * 8);
        }
        CP_COMMIT();
    };

    float acc[4][4][4] = {};

    const int l7 = l & 7;
    const int a_x = l >> 4;
    const int b_x = (l >> 3) & 1;
    int arow[4], bnrow[2];
#pragma unroll
    for (int mi = 0; mi < 4; mi++)
        arow[mi] = (wm * 64 + mi * 16 + (l & 15)) * 128;
#pragma unroll
    for (int g = 0; g < 2; g++)
        bnrow[g] = (wn * 32 + g * 16 + (l >> 4) * 8 + (l & 7)) * 128;

    load_chunk(0, 0);
    load_chunk(1, 1);

    for (int c = 0; c < NCHUNK; c++) {
        if (c + 2 < NCHUNK) {
            asm volatile("cp.async.wait_group 1;" ::: "memory");
        } else {
            asm volatile("cp.async.wait_group 0;" ::: "memory");
        }
        __syncthreads();
        if (c + 2 < NCHUNK) load_chunk(c + 2, (c + 2) % NSTAGE);

        const int s = c % NSTAGE;
        const uint32_t sA = smBase + s * STAGE;
        const uint32_t sB = sA + ATILE;

#pragma unroll
        for (int kk = 0; kk < 4; kk++) {
            uint32_t afr[4][4];
#pragma unroll
            for (int mi = 0; mi < 4; mi++) {
                uint32_t u = (uint32_t)((kk * 2 + a_x) ^ l7);
                ldmx4(afr[mi], sA + arow[mi] + u * 16);
            }
            uint32_t bfr[4][2];
#pragma unroll
            for (int g = 0; g < 2; g++) {
                uint32_t t4[4];
                uint32_t u = (uint32_t)((kk * 2 + b_x) ^ l7);
                ldmx4(t4, sB + bnrow[g] + u * 16);
                bfr[2 * g][0] = t4[0]; bfr[2 * g][1] = t4[1];
                bfr[2 * g + 1][0] = t4[2]; bfr[2 * g + 1][1] = t4[3];
            }
#pragma unroll
            for (int mi = 0; mi < 4; mi++)
#pragma unroll
                for (int ni = 0; ni < 4; ni++)
                    mma16816(acc[mi][ni], afr[mi], bfr[ni]);
        }
        __syncthreads();
    }

    const int crow = l >> 2, ccol = (l & 3) * 2;
#pragma unroll
    for (int mi = 0; mi < 4; mi++) {
#pragma unroll
        for (int ni = 0; ni < 4; ni++) {
            float* p = Cb + (long)(wm * 64 + mi * 16 + crow) * HWD + wn * 32 + ni * 8 + ccol;
            *(float2*)p = make_float2(acc[mi][ni][0], acc[mi][ni][1]);
            *(float2*)(p + 8L * HWD) = make_float2(acc[mi][ni][2], acc[mi][ni][3]);
        }
    }
}

// ---------------------------------------------------------------------------
// Split qkv_w -> A' [1152][1152] bf16 = [hi | lo | hi]
// ---------------------------------------------------------------------------
__global__ void split_w(const float* __restrict__ w, __nv_bfloat16* __restrict__ o)
{
    int idx = blockIdx.x * 256 + threadIdx.x;
    if (idx >= C3 * DIM) return;
    int m = idx / DIM, k = idx % DIM;
    float v = w[idx];
    __nv_bfloat16 hi = __float2bfloat16(v);
    __nv_bfloat16 lo = __float2bfloat16(v - __bfloat162float(hi));
    o[(long)m * KP + k]       = hi;
    o[(long)m * KP + 384 + k] = lo;
    o[(long)m * KP + 768 + k] = hi;
}

// ---------------------------------------------------------------------------
// Split + transpose: src [b][384][HWD] fp32 -> dst [b][HWD][hi|lo] bf16
// ---------------------------------------------------------------------------
__global__ void split_t(const float* __restrict__ src, long bstride,
                        __nv_bfloat16* __restrict__ dst)
{
    __shared__ float t[32][33];
    int n0 = blockIdx.x * 32, c0 = blockIdx.y * 32, b = blockIdx.z;
    int tx = threadIdx.x, ty = threadIdx.y;
    const float* s = src + (long)b * bstride;
#pragma unroll
    for (int i = 0; i < 4; i++) {
        int cl = ty + i * 8;
        t[cl][tx] = s[(long)(c0 + cl) * HWD + n0 + tx];
    }
    __syncthreads();
    __nv_bfloat16* d = dst + (long)b * HWD * 768;
#pragma unroll
    for (int i = 0; i < 4; i++) {
        int nr = ty + i * 8;
        float v = t[tx][nr];
        __nv_bfloat16 hi = __float2bfloat16(v);
        __nv_bfloat16 lo = __float2bfloat16(v - __bfloat162float(hi));
        d[(long)(n0 + nr) * 768 + c0 + tx]       = hi;
        d[(long)(n0 + nr) * 768 + 384 + c0 + tx] = lo;
    }
}

// ---------------------------------------------------------------------------
// Depthwise 3x3 v4: strip-tiled, 4 px/thread, float4 smem loads + stores.
// Zero-padded smem (4 cols each side) -> branchless, aligned, conflict-free.
// ---------------------------------------------------------------------------
__global__ void __launch_bounds__(256)
dwconv3(const float* __restrict__ in, const float* __restrict__ w,
        float* __restrict__ out, float* __restrict__ ssp)
{
    __shared__ float pl[(SROWS + 2) * SPITCH];   // 34 x 136 floats = 18.5KB
    __shared__ float red[256];

    const int strip = blockIdx.x & (NSTRIP - 1);
    const int c = (blockIdx.x >> 2) % C3;
    const int b = blockIdx.x / (NSTRIP * C3);
    const int tid = threadIdx.x;

    // zero full smem tile (covers halo rows at image edges + side pads)
#pragma unroll
    for (int i = tid; i < (SROWS + 2) * SPITCH; i += 256)
        pl[i] = 0.f;
    __syncthreads();

    const int r0 = strip * SROWS;
    const float* ip = in + ((long)b * C3 + c) * HWD;

    // load rows [r0-1, r0+SROWS] (clipped) into smem rows [0, 33], col offset 4
    {
        const int rlo = (strip == 0) ? 1 : 0;
        const int rhi = (strip == NSTRIP - 1) ? SROWS : SROWS + 1;
        const int njobs = (rhi - rlo + 1) * 32;          // float4 jobs
        for (int i = tid; i < njobs; i += 256) {
            int lr = rlo + (i >> 5);
            int x4 = (i & 31) * 4;
            *(float4*)&pl[lr * SPITCH + 4 + x4] =
                *(const float4*)&ip[(long)(r0 - 1 + lr) * 128 + x4];
        }
    }

    const float* wp = w + c * 9;
    float w0 = wp[0], w1 = wp[1], w2 = wp[2];
    float w3 = wp[3], w4 = wp[4], w5 = wp[5];
    float w6 = wp[6], w7 = wp[7], w8 = wp[8];
    __syncthreads();

    float4* op4 = (float4*)(out + ((long)b * C3 + c) * HWD + (long)r0 * 128);
    float ss = 0.f;
#pragma unroll
    for (int it = 0; it < 4; it++) {
        int q = it * 256 + tid;                  // float4 index 0..1023
        int h = q >> 5, x = (q & 31) * 4;
        int idx = (h + 1) * SPITCH + 4 + x;
        float4 a0 = *(float4*)&pl[idx - SPITCH - 4];
        float4 b0 = *(float4*)&pl[idx - SPITCH];
        float4 c0 = *(float4*)&pl[idx - SPITCH + 4];
        float4 a1 = *(float4*)&pl[idx - 4];
        float4 b1 = *(float4*)&pl[idx];
        float4 c1 = *(float4*)&pl[idx + 4];
        float4 a2 = *(float4*)&pl[idx + SPITCH - 4];
        float4 b2 = *(float4*)&pl[idx + SPITCH];
        float4 c2 = *(float4*)&pl[idx + SPITCH + 4];
        float4 s;
        s.x = w0 * a0.w + w1 * b0.x + w2 * b0.y
            + w3 * a1.w + w4 * b1.x + w5 * b1.y
            + w6 * a2.w + w7 * b2.x + w8 * b2.y;
        s.y = w0 * b0.x + w1 * b0.y + w2 * b0.z
            + w3 * b1.x + w4 * b1.y + w5 * b1.z
            + w6 * b2.x + w7 * b2.y + w8 * b2.z;
        s.z = w0 * b0.y + w1 * b0.z + w2 * b0.w
            + w3 * b1.y + w4 * b1.z + w5 * b1.w
            + w6 * b2.y + w7 * b2.z + w8 * b2.w;
        s.w = w0 * b0.z + w1 * b0.w + w2 * c0.x
            + w3 * b1.z + w4 * b1.w + w5 * c1.x
            + w6 * b2.z + w7 * b2.w + w8 * c2.x;
        op4[q] = s;
        ss += s.x * s.x + s.y * s.y + s.z * s.z + s.w * s.w;
    }

    if (c < 768) {
        red[tid] = ss;
        __syncthreads();
        for (int st = 128; st > 0; st >>= 1) {
            if (tid < st) red[tid] += red[tid + st];
            __syncthreads();
        }
        if (tid == 0)
            ssp[(b * 768 + c) * NSTRIP + strip] = red[0];
    }
}

// finalize inv norms from strip partials
__global__ void norm_fin(const float* __restrict__ ssp, float* __restrict__ inv)
{
    int i = blockIdx.x * 256 + threadIdx.x;
    if (i >= BATCH * 768) return;
    float s = 0.f;
#pragma unroll
    for (int j = 0; j < NSTRIP; j++) s += ssp[i * NSTRIP + j];
    inv[i] = 1.f / fmaxf(sqrtf(s), 1e-12f);
}

// ---------------------------------------------------------------------------
// Gram partial (unchanged)
// ---------------------------------------------------------------------------
__global__ void __launch_bounds__(256)
gram_partial(const float* __restrict__ qkv2, float* __restrict__ gpart)
{
    const int chunk = blockIdx.x;
    const int bh = blockIdx.y;
    const int b = bh >> 3, h = bh & 7;
    const float* qb = qkv2 + ((long)b * C3 + h * CH) * HWD;
    const float* kb = qb + (long)DIM * HWD;

    __shared__ float qs[64][49], ks[64][49];
    const int tid = threadIdx.x;
    const int tx = tid & 15, ty = tid >> 4;
    float acc[3][3] = {};

    const int n0 = chunk * 512;
    for (int slab = 0; slab < 8; slab++) {
        const int base = n0 + slab * 64;
        __syncthreads();
#pragma unroll
        for (int j = 0; j < 3; j++) {
            int id = tid + j * 256;
            int rid = id >> 4, c4 = id & 15;
            float4 v = *(const float4*)(qb + (long)rid * HWD + base + c4 * 4);
            qs[c4 * 4 + 0][rid] = v.x; qs[c4 * 4 + 1][rid] = v.y;
            qs[c4 * 4 + 2][rid] = v.z; qs[c4 * 4 + 3][rid] = v.w;
            float4 u = *(const float4*)(kb + (long)rid * HWD + base + c4 * 4);
            ks[c4 * 4 + 0][rid] = u.x; ks[c4 * 4 + 1][rid] = u.y;
            ks[c4 * 4 + 2][rid] = u.z; ks[c4 * 4 + 3][rid] = u.w;
        }
        __syncthreads();
#pragma unroll 8
        for (int t = 0; t < 64; t++) {
            float qa[3], ka[3];
#pragma unroll
            for (int i = 0; i < 3; i++) qa[i] = qs[t][ty * 3 + i];
#pragma unroll
            for (int j = 0; j < 3; j++) ka[j] = ks[t][tx * 3 + j];
#pragma unroll
            for (int i = 0; i < 3; i++)
#pragma unroll
                for (int j = 0; j < 3; j++)
                    acc[i][j] += qa[i] * ka[j];
        }
    }
    float* op = gpart + ((long)chunk * 64 + bh) * (CH * CH);
#pragma unroll
    for (int i = 0; i < 3; i++)
#pragma unroll
        for (int j = 0; j < 3; j++)
            op[(ty * 3 + i) * CH + tx * 3 + j] = acc[i][j];
}

__global__ void gram_scale(const float* __restrict__ gpart, const float* __restrict__ inv,
                           const float* __restrict__ temp, float* __restrict__ attn)
{
    int idx = blockIdx.x * 256 + threadIdx.x;
    if (idx >= 64 * CH * CH) return;
    int bh = idx / (CH * CH), r = idx % (CH * CH);
    int c = r / CH, d = r % CH;
    int b = bh >> 3, h = bh & 7;
    float s = 0.f;
#pragma unroll
    for (int ck = 0; ck < GCH; ck++) s += gpart[((long)ck * 64 + bh) * (CH * CH) + r];
    float iq = inv[b * 768 + h * CH + c];
    float ik = inv[b * 768 + 384 + h * CH + d];
    attn[idx] = s * iq * ik * temp[h];
}

__global__ void topk_softmax(float* __restrict__ attn)
{
    int row = blockIdx.x;
    float* p = attn + (long)row * CH;
    __shared__ float s[CH], e[CH];
    int i = threadIdx.x;
    if (i < CH) s[i] = p[i];
    __syncthreads();
    if (i < CH) {
        float v = s[i];
        int cnt = 0;
        float m = -1e30f;
#pragma unroll
        for (int j = 0; j < CH; j++) {
            cnt += (s[j] > v);
            m = fmaxf(m, s[j]);
        }
        e[i] = (cnt < TOPKN) ? expf(v - m) : 0.f;
    }
    __syncthreads();
    if (i < CH) {
        float sum = 0.f;
#pragma unroll
        for (int j = 0; j < CH; j++) sum += e[j];
        p[i] = e[i] / sum;
    }
}

// ---------------------------------------------------------------------------
// Fold proj_w @ blockdiag(attn) -> Wbs (bf16 split [hi|lo|hi])
// ---------------------------------------------------------------------------
__global__ void fold_proj(const float* __restrict__ projw, const float* __restrict__ attn,
                          __nv_bfloat16* __restrict__ Wbs)
{
    int idx = blockIdx.x * 256 + threadIdx.x;
    if (idx >= BATCH * DIM * DIM) return;
    int b = idx / (DIM * DIM);
    int r = idx % (DIM * DIM);
    int o = r / DIM, dg = r % DIM;
    int h = dg / CH, d = dg % CH;
    const float* pw = projw + o * DIM + h * CH;
    const float* at = attn + ((long)(b * NH + h) * CH) * CH + d;
    float s = 0.f;
#pragma unroll
    for (int c = 0; c < CH; c++) s += pw[c] * at[c * CH];
    __nv_bfloat16 hi = __float2bfloat16(s);
    __nv_bfloat16 lo = __float2bfloat16(s - __bfloat162float(hi));
    __nv_bfloat16* row = Wbs + ((long)b * DIM + o) * KP;
    row[dg]       = hi;
    row[384 + dg] = lo;
    row[768 + dg] = hi;
}

// ---------------------------------------------------------------------------
extern "C" void kernel_launch(void* const* d_in, const int* in_sizes, int n_in,
                              void* d_out, int out_size)
{
    const float* x      = (const float*)d_in[0];
    const float* qkv_w  = (const float*)d_in[1];
    const float* dw_w   = (const float*)d_in[2];
    const float* proj_w = (const float*)d_in[3];
    const float* temp   = (const float*)d_in[4];
    float* out = (float*)d_out;

    float *qkv1, *qkv2, *ssp, *inv, *gpart, *attn;
    __nv_bfloat16 *A1, *xs, *vs, *Wbs;
    cudaGetSymbolAddress((void**)&qkv1,  g_qkv1);
    cudaGetSymbolAddress((void**)&qkv2,  g_qkv2);
    cudaGetSymbolAddress((void**)&ssp,   g_ssp);
    cudaGetSymbolAddress((void**)&inv,   g_inv);
    cudaGetSymbolAddress((void**)&gpart, g_gpart);
    cudaGetSymbolAddress((void**)&attn,  g_attn);
    cudaGetSymbolAddress((void**)&A1,    g_A1);
    cudaGetSymbolAddress((void**)&xs,    g_xs);
    cudaGetSymbolAddress((void**)&vs,    g_vs);
    cudaGetSymbolAddress((void**)&Wbs,   g_Wbs);

    cudaFuncSetAttribute(gemm_split, cudaFuncAttributeMaxDynamicSharedMemorySize, GEMM_SMEM);

    // 0) operand splits
    split_w<<<(C3 * DIM + 255) / 256, 256>>>(qkv_w, A1);
    split_t<<<dim3(HWD / 32, DIM / 32, BATCH), dim3(32, 8)>>>(x, (long)DIM * HWD, xs);

    // 1) qkv = qkv_w @ x  (bf16 mma.sync, split precision)
    gemm_split<<<dim3(C3 / BM, HWD / BN, BATCH), 256, GEMM_SMEM>>>(
        A1, 0L, xs, qkv1, (long)C3 * HWD);

    // 2) depthwise 3x3 (strip-tiled, vectorized) + partial norms, then finalize
    dwconv3<<<BATCH * C3 * NSTRIP, 256>>>(qkv1, dw_w, qkv2, ssp);
    norm_fin<<<(BATCH * 768 + 255) / 256, 256>>>(ssp, inv);

    // 3) split v for final GEMM
    split_t<<<dim3(HWD / 32, DIM / 32, BATCH), dim3(32, 8)>>>(
        qkv2 + (size_t)2 * DIM * HWD, (long)C3 * HWD, vs);

    // 4) Gram + scale
    gram_partial<<<dim3(GCH, BATCH * NH), 256>>>(qkv2, gpart);
    gram_scale<<<(64 * CH * CH + 255) / 256, 256>>>(gpart, inv, temp, attn);

    // 5) top-7 + softmax
    topk_softmax<<<BATCH * NH * CH, 64>>>(attn);

    // 6) fold proj @ blockdiag(attn) -> bf16 split
    fold_proj<<<(BATCH * DIM * DIM + 255) / 256, 256>>>(proj_w, attn, Wbs);

    // 7) out = Wb @ v  (bf16 mma.sync, split precision)
    gemm_split<<<dim3(DIM / BM, HWD / BN, BATCH), 256, GEMM_SMEM>>>(
        Wbs, (long)DIM * KP, vs, out, (long)DIM * HWD);
}

// round 11
// speedup vs baseline: 4.0734x; 1.0337x over previous
#include <cuda_runtime.h>
#include <cuda_bf16.h>
#include <math.h>
#include <stdint.h>

// ---------------------------------------------------------------------------
// Problem constants
// ---------------------------------------------------------------------------
constexpr int BATCH = 8;
constexpr int DIM   = 384;
constexpr int NH    = 8;
constexpr int CH    = 48;
constexpr int HWD   = 16384;  // 128*128
constexpr int C3    = 1152;
constexpr int TOPKN = 7;

// split-precision GEMM constants
constexpr int KP     = 1152;
constexpr int KC     = 64;
constexpr int NCHUNK = KP / KC;  // 18
constexpr int BM     = 128;
constexpr int BN     = 128;
constexpr int ATILE  = BM * 128;
constexpr int BTILE  = BN * 128;
constexpr int STAGE  = ATILE + BTILE;       // 32 KB
constexpr int NSTAGE = 3;
constexpr int GEMM_SMEM = NSTAGE * STAGE;   // 96 KB

constexpr int GCH = 32;        // gram chunks

// dwconv strips
constexpr int SROWS = 32;                 // output rows per block
constexpr int NSTRIP = 128 / SROWS;       // 4
constexpr int SPITCH = 136;               // smem row pitch (4 zero cols each side)

// ---------------------------------------------------------------------------
// Scratch (device globals)
// ---------------------------------------------------------------------------
__device__ float g_qkv1[(size_t)BATCH * C3 * HWD];
__device__ float g_qkv2[(size_t)BATCH * C3 * HWD];
__device__ float g_ssp[BATCH * 768 * NSTRIP];           // partial sum-of-squares
__device__ float g_inv[BATCH * 768];                    // [b][c] c<384: q, c>=384: k
__device__ float g_gpart[(size_t)GCH * BATCH * NH * CH * CH];
__device__ float g_attn[BATCH * NH * CH * CH];
__device__ __nv_bfloat16 g_A1[(size_t)C3 * KP];
__device__ __nv_bfloat16 g_xs[(size_t)BATCH * HWD * 768];
__device__ __nv_bfloat16 g_vs[(size_t)BATCH * HWD * 768];
__device__ __nv_bfloat16 g_Wbs[(size_t)BATCH * DIM * KP];

// ---------------------------------------------------------------------------
// sm_80-portable PTX helpers
// ---------------------------------------------------------------------------
__device__ __forceinline__ uint32_t smem_u32(const void* p) {
    uint32_t a;
    asm("{ .reg .u64 t; cvta.to.shared.u64 t, %1; cvt.u32.u64 %0, t; }" : "=r"(a) : "l"(p));
    return a;
}

__device__ __forceinline__ void cp16(uint32_t saddr, const void* gaddr) {
    asm volatile("cp.async.cg.shared.global [%0], [%1], 16;" :: "r"(saddr), "l"(gaddr));
}
#define CP_COMMIT() asm volatile("cp.async.commit_group;" ::: "memory")

__device__ __forceinline__ void ldmx4(uint32_t* r, uint32_t addr) {
    asm volatile("ldmatrix.sync.aligned.m8n8.x4.shared.b16 {%0,%1,%2,%3}, [%4];"
                 : "=r"(r[0]), "=r"(r[1]), "=r"(r[2]), "=r"(r[3]) : "r"(addr));
}

__device__ __forceinline__ void mma16816(float* c, const uint32_t* a, const uint32_t* b) {
    asm volatile(
        "mma.sync.aligned.m16n8k16.row.col.f32.bf16.bf16.f32 "
        "{%0,%1,%2,%3}, {%4,%5,%6,%7}, {%8,%9}, {%0,%1,%2,%3};"
        : "+f"(c[0]), "+f"(c[1]), "+f"(c[2]), "+f"(c[3])
        : "r"(a[0]), "r"(a[1]), "r"(a[2]), "r"(a[3]), "r"(b[0]), "r"(b[1]));
}

// ---------------------------------------------------------------------------
// Split-precision bf16 tensor-core GEMM (unchanged)
// ---------------------------------------------------------------------------
__global__ void __launch_bounds__(256, 2)
gemm_split(const __nv_bfloat16* __restrict__ A, long aBatchStride,
           const __nv_bfloat16* __restrict__ B,
           float* __restrict__ C, long cBatchStride)
{
    extern __shared__ char sm[];
    const uint32_t smBase = smem_u32(sm);

    const int tid = threadIdx.x;
    const int wid = tid >> 5, l = tid & 31;
    const int wm = wid >> 2, wn = wid & 3;
    const int bm0 = blockIdx.x * BM;
    const int bn0 = blockIdx.y * BN;
    const int bz  = blockIdx.z;

    const __nv_bfloat16* Ab = A + (long)bz * aBatchStride + (long)bm0 * KP;
    const __nv_bfloat16* Bb = B + ((long)bz * HWD + bn0) * 768;
    float* Cb = C + (long)bz * cBatchStride + (long)bm0 * HWD + bn0;

    const int ldr = tid >> 3, ldq = tid & 7;

    auto load_chunk = [&](int c, int s) {
        const uint32_t sA = smBase + s * STAGE;
        const uint32_t sB = sA + ATILE;
        const __nv_bfloat16* ac = Ab + c * KC;
        const int bk = (c < 6) ? c * KC : c * KC - 384;
        const __nv_bfloat16* bc = Bb + bk;
#pragma unroll
        for (int i = 0; i < 4; i++) {
            int r = ldr + i * 32;
            int u = ldq ^ (r & 7);
            cp16(sA + r * 128 + u * 16, ac + (long)r * KP + ldq * 8);
        }
#pragma unroll
        for (int i = 0; i < 4; i++) {
            int r = ldr + i * 32;
            int u = ldq ^ (r & 7);
            cp16(sB + r * 128 + u * 16, bc + (long)r * 768 + ldq * 8);
        }
        CP_COMMIT();
    };

    float acc[4][4][4] = {};

    const int l7 = l & 7;
    const int a_x = l >> 4;
    const int b_x = (l >> 3) & 1;
    int arow[4], bnrow[2];
#pragma unroll
    for (int mi = 0; mi < 4; mi++)
        arow[mi] = (wm * 64 + mi * 16 + (l & 15)) * 128;
#pragma unroll
    for (int g = 0; g < 2; g++)
        bnrow[g] = (wn * 32 + g * 16 + (l >> 4) * 8 + (l & 7)) * 128;

    load_chunk(0, 0);
    load_chunk(1, 1);

    for (int c = 0; c < NCHUNK; c++) {
        if (c + 2 < NCHUNK) {
            asm volatile("cp.async.wait_group 1;" ::: "memory");
        } else {
            asm volatile("cp.async.wait_group 0;" ::: "memory");
        }
        __syncthreads();
        if (c + 2 < NCHUNK) load_chunk(c + 2, (c + 2) % NSTAGE);

        const int s = c % NSTAGE;
        const uint32_t sA = smBase + s * STAGE;
        const uint32_t sB = sA + ATILE;

#pragma unroll
        for (int kk = 0; kk < 4; kk++) {
            uint32_t afr[4][4];
#pragma unroll
            for (int mi = 0; mi < 4; mi++) {
                uint32_t u = (uint32_t)((kk * 2 + a_x) ^ l7);
                ldmx4(afr[mi], sA + arow[mi] + u * 16);
            }
            uint32_t bfr[4][2];
#pragma unroll
            for (int g = 0; g < 2; g++) {
                uint32_t t4[4];
                uint32_t u = (uint32_t)((kk * 2 + b_x) ^ l7);
                ldmx4(t4, sB + bnrow[g] + u * 16);
                bfr[2 * g][0] = t4[0]; bfr[2 * g][1] = t4[1];
                bfr[2 * g + 1][0] = t4[2]; bfr[2 * g + 1][1] = t4[3];
            }
#pragma unroll
            for (int mi = 0; mi < 4; mi++)
#pragma unroll
                for (int ni = 0; ni < 4; ni++)
                    mma16816(acc[mi][ni], afr[mi], bfr[ni]);
        }
        __syncthreads();
    }

    const int crow = l >> 2, ccol = (l & 3) * 2;
#pragma unroll
    for (int mi = 0; mi < 4; mi++) {
#pragma unroll
        for (int ni = 0; ni < 4; ni++) {
            float* p = Cb + (long)(wm * 64 + mi * 16 + crow) * HWD + wn * 32 + ni * 8 + ccol;
            *(float2*)p = make_float2(acc[mi][ni][0], acc[mi][ni][1]);
            *(float2*)(p + 8L * HWD) = make_float2(acc[mi][ni][2], acc[mi][ni][3]);
        }
    }
}

// ---------------------------------------------------------------------------
// Split qkv_w -> A' [1152][1152] bf16 = [hi | lo | hi]
// ---------------------------------------------------------------------------
__global__ void split_w(const float* __restrict__ w, __nv_bfloat16* __restrict__ o)
{
    int idx = blockIdx.x * 256 + threadIdx.x;
    if (idx >= C3 * DIM) return;
    int m = idx / DIM, k = idx % DIM;
    float v = w[idx];
    __nv_bfloat16 hi = __float2bfloat16(v);
    __nv_bfloat16 lo = __float2bfloat16(v - __bfloat162float(hi));
    o[(long)m * KP + k]       = hi;
    o[(long)m * KP + 384 + k] = lo;
    o[(long)m * KP + 768 + k] = hi;
}

// ---------------------------------------------------------------------------
// Split + transpose: src [b][384][HWD] fp32 -> dst [b][HWD][hi|lo] bf16
// ---------------------------------------------------------------------------
__global__ void split_t(const float* __restrict__ src, long bstride,
                        __nv_bfloat16* __restrict__ dst)
{
    __shared__ float t[32][33];
    int n0 = blockIdx.x * 32, c0 = blockIdx.y * 32, b = blockIdx.z;
    int tx = threadIdx.x, ty = threadIdx.y;
    const float* s = src + (long)b * bstride;
#pragma unroll
    for (int i = 0; i < 4; i++) {
        int cl = ty + i * 8;
        t[cl][tx] = s[(long)(c0 + cl) * HWD + n0 + tx];
    }
    __syncthreads();
    __nv_bfloat16* d = dst + (long)b * HWD * 768;
#pragma unroll
    for (int i = 0; i < 4; i++) {
        int nr = ty + i * 8;
        float v = t[tx][nr];
        __nv_bfloat16 hi = __float2bfloat16(v);
        __nv_bfloat16 lo = __float2bfloat16(v - __bfloat162float(hi));
        d[(long)(n0 + nr) * 768 + c0 + tx]       = hi;
        d[(long)(n0 + nr) * 768 + 384 + c0 + tx] = lo;
    }
}

// ---------------------------------------------------------------------------
// Depthwise 3x3 v5: strip-tiled, 4x4 px/thread, sliding 3-row register window.
// 18 LDS.128 per 16 outputs (was 36). Zero-padded smem -> branchless.
// ---------------------------------------------------------------------------
__global__ void __launch_bounds__(256)
dwconv3(const float* __restrict__ in, const float* __restrict__ w,
        float* __restrict__ out, float* __restrict__ ssp)
{
    __shared__ float pl[(SROWS + 2) * SPITCH];   // 34 x 136 floats = 18.5KB
    __shared__ float red[256];

    const int strip = blockIdx.x & (NSTRIP - 1);
    const int c = (blockIdx.x >> 2) % C3;
    const int b = blockIdx.x / (NSTRIP * C3);
    const int tid = threadIdx.x;

    // zero full smem tile (covers halo rows at image edges + side pads)
#pragma unroll
    for (int i = tid; i < (SROWS + 2) * SPITCH; i += 256)
        pl[i] = 0.f;
    __syncthreads();

    const int r0 = strip * SROWS;
    const float* ip = in + ((long)b * C3 + c) * HWD;

    // load rows [r0-1, r0+SROWS] (clipped) into smem rows [0, 33], col offset 4
    {
        const int rlo = (strip == 0) ? 1 : 0;
        const int rhi = (strip == NSTRIP - 1) ? SROWS : SROWS + 1;
        const int njobs = (rhi - rlo + 1) * 32;          // float4 jobs
        for (int i = tid; i < njobs; i += 256) {
            int lr = rlo + (i >> 5);
            int x4 = (i & 31) * 4;
            *(float4*)&pl[lr * SPITCH + 4 + x4] =
                *(const float4*)&ip[(long)(r0 - 1 + lr) * 128 + x4];
        }
    }

    const float* wp = w + c * 9;
    float w0 = wp[0], w1 = wp[1], w2 = wp[2];
    float w3 = wp[3], w4 = wp[4], w5 = wp[5];
    float w6 = wp[6], w7 = wp[7], w8 = wp[8];
    __syncthreads();

    // 4x4 patch per thread: tx -> x block, ty -> row block
    const int tx = tid & 31, ty = tid >> 5;
    const int x4 = tx * 4;
    const int h0 = ty * 4;

    float4 Ar[3], Br[3], Cr[3];       // sliding window: left / center / right
    auto loadrow = [&](int srow, int slot) {
        int idx = srow * SPITCH + 4 + x4;
        Ar[slot] = *(float4*)&pl[idx - 4];
        Br[slot] = *(float4*)&pl[idx];
        Cr[slot] = *(float4*)&pl[idx + 4];
    };
    loadrow(h0 + 0, 0);
    loadrow(h0 + 1, 1);
    loadrow(h0 + 2, 2);

    float4* op4 = (float4*)(out + ((long)b * C3 + c) * HWD + (long)r0 * 128);
    float ss = 0.f;

#pragma unroll
    for (int i = 0; i < 4; i++) {
        const int s0 = i % 3, s1 = (i + 1) % 3, s2 = (i + 2) % 3;
        float4 s;
        s.x = w0 * Ar[s0].w + w1 * Br[s0].x + w2 * Br[s0].y
            + w3 * Ar[s1].w + w4 * Br[s1].x + w5 * Br[s1].y
            + w6 * Ar[s2].w + w7 * Br[s2].x + w8 * Br[s2].y;
        s.y = w0 * Br[s0].x + w1 * Br[s0].y + w2 * Br[s0].z
            + w3 * Br[s1].x + w4 * Br[s1].y + w5 * Br[s1].z
            + w6 * Br[s2].x + w7 * Br[s2].y + w8 * Br[s2].z;
        s.z = w0 * Br[s0].y + w1 * Br[s0].z + w2 * Br[s0].w
            + w3 * Br[s1].y + w4 * Br[s1].z + w5 * Br[s1].w
            + w6 * Br[s2].y + w7 * Br[s2].z + w8 * Br[s2].w;
        s.w = w0 * Br[s0].z + w1 * Br[s0].w + w2 * Cr[s0].x
            + w3 * Br[s1].z + w4 * Br[s1].w + w5 * Cr[s1].x
            + w6 * Br[s2].z + w7 * Br[s2].w + w8 * Cr[s2].x;
        op4[(h0 + i) * 32 + tx] = s;
        ss += s.x * s.x + s.y * s.y + s.z * s.z + s.w * s.w;
        if (i < 3) loadrow(h0 + 3 + i, s0);      // slide window
    }

    if (c < 768) {
        red[tid] = ss;
        __syncthreads();
        for (int st = 128; st > 0; st >>= 1) {
            if (tid < st) red[tid] += red[tid + st];
            __syncthreads();
        }
        if (tid == 0)
            ssp[(b * 768 + c) * NSTRIP + strip] = red[0];
    }
}

// finalize inv norms from strip partials
__global__ void norm_fin(const float* __restrict__ ssp, float* __restrict__ inv)
{
    int i = blockIdx.x * 256 + threadIdx.x;
    if (i >= BATCH * 768) return;
    float s = 0.f;
#pragma unroll
    for (int j = 0; j < NSTRIP; j++) s += ssp[i * NSTRIP + j];
    inv[i] = 1.f / fmaxf(sqrtf(s), 1e-12f);
}

// ---------------------------------------------------------------------------
// Gram partial (unchanged)
// ---------------------------------------------------------------------------
__global__ void __launch_bounds__(256)
gram_partial(const float* __restrict__ qkv2, float* __restrict__ gpart)
{
    const int chunk = blockIdx.x;
    const int bh = blockIdx.y;
    const int b = bh >> 3, h = bh & 7;
    const float* qb = qkv2 + ((long)b * C3 + h * CH) * HWD;
    const float* kb = qb + (long)DIM * HWD;

    __shared__ float qs[64][49], ks[64][49];
    const int tid = threadIdx.x;
    const int tx = tid & 15, ty = tid >> 4;
    float acc[3][3] = {};

    const int n0 = chunk * 512;
    for (int slab = 0; slab < 8; slab++) {
        const int base = n0 + slab * 64;
        __syncthreads();
#pragma unroll
        for (int j = 0; j < 3; j++) {
            int id = tid + j * 256;
            int rid = id >> 4, c4 = id & 15;
            float4 v = *(const float4*)(qb + (long)rid * HWD + base + c4 * 4);
            qs[c4 * 4 + 0][rid] = v.x; qs[c4 * 4 + 1][rid] = v.y;
            qs[c4 * 4 + 2][rid] = v.z; qs[c4 * 4 + 3][rid] = v.w;
            float4 u = *(const float4*)(kb + (long)rid * HWD + base + c4 * 4);
            ks[c4 * 4 + 0][rid] = u.x; ks[c4 * 4 + 1][rid] = u.y;
            ks[c4 * 4 + 2][rid] = u.z; ks[c4 * 4 + 3][rid] = u.w;
        }
        __syncthreads();
#pragma unroll 8
        for (int t = 0; t < 64; t++) {
            float qa[3], ka[3];
#pragma unroll
            for (int i = 0; i < 3; i++) qa[i] = qs[t][ty * 3 + i];
#pragma unroll
            for (int j = 0; j < 3; j++) ka[j] = ks[t][tx * 3 + j];
#pragma unroll
            for (int i = 0; i < 3; i++)
#pragma unroll
                for (int j = 0; j < 3; j++)
                    acc[i][j] += qa[i] * ka[j];
        }
    }
    float* op = gpart + ((long)chunk * 64 + bh) * (CH * CH);
#pragma unroll
    for (int i = 0; i < 3; i++)
#pragma unroll
        for (int j = 0; j < 3; j++)
            op[(ty * 3 + i) * CH + tx * 3 + j] = acc[i][j];
}

__global__ void gram_scale(const float* __restrict__ gpart, const float* __restrict__ inv,
                           const float* __restrict__ temp, float* __restrict__ attn)
{
    int idx = blockIdx.x * 256 + threadIdx.x;
    if (idx >= 64 * CH * CH) return;
    int bh = idx / (CH * CH), r = idx % (CH * CH);
    int c = r / CH, d = r % CH;
    int b = bh >> 3, h = bh & 7;
    float s = 0.f;
#pragma unroll
    for (int ck = 0; ck < GCH; ck++) s += gpart[((long)ck * 64 + bh) * (CH * CH) + r];
    float iq = inv[b * 768 + h * CH + c];
    float ik = inv[b * 768 + 384 + h * CH + d];
    attn[idx] = s * iq * ik * temp[h];
}

__global__ void topk_softmax(float* __restrict__ attn)
{
    int row = blockIdx.x;
    float* p = attn + (long)row * CH;
    __shared__ float s[CH], e[CH];
    int i = threadIdx.x;
    if (i < CH) s[i] = p[i];
    __syncthreads();
    if (i < CH) {
        float v = s[i];
        int cnt = 0;
        float m = -1e30f;
#pragma unroll
        for (int j = 0; j < CH; j++) {
            cnt += (s[j] > v);
            m = fmaxf(m, s[j]);
        }
        e[i] = (cnt < TOPKN) ? expf(v - m) : 0.f;
    }
    __syncthreads();
    if (i < CH) {
        float sum = 0.f;
#pragma unroll
        for (int j = 0; j < CH; j++) sum += e[j];
        p[i] = e[i] / sum;
    }
}

// ---------------------------------------------------------------------------
// Fold proj_w @ blockdiag(attn) -> Wbs (bf16 split [hi|lo|hi])
// ---------------------------------------------------------------------------
__global__ void fold_proj(const float* __restrict__ projw, const float* __restrict__ attn,
                          __nv_bfloat16* __restrict__ Wbs)
{
    int idx = blockIdx.x * 256 + threadIdx.x;
    if (idx >= BATCH * DIM * DIM) return;
    int b = idx / (DIM * DIM);
    int r = idx % (DIM * DIM);
    int o = r / DIM, dg = r % DIM;
    int h = dg / CH, d = dg % CH;
    const float* pw = projw + o * DIM + h * CH;
    const float* at = attn + ((long)(b * NH + h) * CH) * CH + d;
    float s = 0.f;
#pragma unroll
    for (int c = 0; c < CH; c++) s += pw[c] * at[c * CH];
    __nv_bfloat16 hi = __float2bfloat16(s);
    __nv_bfloat16 lo = __float2bfloat16(s - __bfloat162float(hi));
    __nv_bfloat16* row = Wbs + ((long)b * DIM + o) * KP;
    row[dg]       = hi;
    row[384 + dg] = lo;
    row[768 + dg] = hi;
}

// ---------------------------------------------------------------------------
extern "C" void kernel_launch(void* const* d_in, const int* in_sizes, int n_in,
                              void* d_out, int out_size)
{
    const float* x      = (const float*)d_in[0];
    const float* qkv_w  = (const float*)d_in[1];
    const float* dw_w   = (const float*)d_in[2];
    const float* proj_w = (const float*)d_in[3];
    const float* temp   = (const float*)d_in[4];
    float* out = (float*)d_out;

    float *qkv1, *qkv2, *ssp, *inv, *gpart, *attn;
    __nv_bfloat16 *A1, *xs, *vs, *Wbs;
    cudaGetSymbolAddress((void**)&qkv1,  g_qkv1);
    cudaGetSymbolAddress((void**)&qkv2,  g_qkv2);
    cudaGetSymbolAddress((void**)&ssp,   g_ssp);
    cudaGetSymbolAddress((void**)&inv,   g_inv);
    cudaGetSymbolAddress((void**)&gpart, g_gpart);
    cudaGetSymbolAddress((void**)&attn,  g_attn);
    cudaGetSymbolAddress((void**)&A1,    g_A1);
    cudaGetSymbolAddress((void**)&xs,    g_xs);
    cudaGetSymbolAddress((void**)&vs,    g_vs);
    cudaGetSymbolAddress((void**)&Wbs,   g_Wbs);

    cudaFuncSetAttribute(gemm_split, cudaFuncAttributeMaxDynamicSharedMemorySize, GEMM_SMEM);

    // 0) operand splits
    split_w<<<(C3 * DIM + 255) / 256, 256>>>(qkv_w, A1);
    split_t<<<dim3(HWD / 32, DIM / 32, BATCH), dim3(32, 8)>>>(x, (long)DIM * HWD, xs);

    // 1) qkv = qkv_w @ x  (bf16 mma.sync, split precision)
    gemm_split<<<dim3(C3 / BM, HWD / BN, BATCH), 256, GEMM_SMEM>>>(
        A1, 0L, xs, qkv1, (long)C3 * HWD);

    // 2) depthwise 3x3 (strip-tiled, 4x4/thread) + partial norms, then finalize
    dwconv3<<<BATCH * C3 * NSTRIP, 256>>>(qkv1, dw_w, qkv2, ssp);
    norm_fin<<<(BATCH * 768 + 255) / 256, 256>>>(ssp, inv);

    // 3) split v for final GEMM
    split_t<<<dim3(HWD / 32, DIM / 32, BATCH), dim3(32, 8)>>>(
        qkv2 + (size_t)2 * DIM * HWD, (long)C3 * HWD, vs);

    // 4) Gram + scale
    gram_partial<<<dim3(GCH, BATCH * NH), 256>>>(qkv2, gpart);
    gram_scale<<<(64 * CH * CH + 255) / 256, 256>>>(gpart, inv, temp, attn);

    // 5) top-7 + softmax
    topk_softmax<<<BATCH * NH * CH, 64>>>(attn);

    // 6) fold proj @ blockdiag(attn) -> bf16 split
    fold_proj<<<(BATCH * DIM * DIM + 255) / 256, 256>>>(proj_w, attn, Wbs);

    // 7) out = Wb @ v  (bf16 mma.sync, split precision)
    gemm_split<<<dim3(DIM / BM, HWD / BN, BATCH), 256, GEMM_SMEM>>>(
        Wbs, (long)DIM * KP, vs, out, (long)DIM * HWD);
}

// round 12
// speedup vs baseline: 4.1580x; 1.0208x over previous
#include <cuda_runtime.h>
#include <cuda_bf16.h>
#include <math.h>
#include <stdint.h>

// ---------------------------------------------------------------------------
// Problem constants
// ---------------------------------------------------------------------------
constexpr int BATCH = 8;
constexpr int DIM   = 384;
constexpr int NH    = 8;
constexpr int CH    = 48;
constexpr int HWD   = 16384;  // 128*128
constexpr int C3    = 1152;
constexpr int TOPKN = 7;

// split-precision GEMM constants
constexpr int KP     = 1152;     // K' = 3*384 (hi*hi, lo*hi, hi*lo)
constexpr int KC     = 64;
constexpr int NCHUNK = KP / KC;  // 18
constexpr int BM     = 128;
constexpr int BN     = 128;
constexpr int ATILE  = BM * 128;       // A: 128 rows x 128B (k-contig rows)
constexpr int BTILE  = KC * 256;       // B: 64 k-rows x 256B (n-contig rows)
constexpr int STAGE  = ATILE + BTILE;  // 32 KB
constexpr int NSTAGE = 3;
constexpr int GEMM_SMEM = NSTAGE * STAGE;   // 96 KB

constexpr int GCH = 32;        // gram chunks

// dwconv strips
constexpr int SROWS = 32;
constexpr int NSTRIP = 128 / SROWS;       // 4
constexpr int SPITCH = 136;

// ---------------------------------------------------------------------------
// Scratch (device globals)
// ---------------------------------------------------------------------------
__device__ float g_qkv1[(size_t)BATCH * C3 * HWD];
__device__ float g_qkv2[(size_t)BATCH * C3 * HWD];   // only q,k region used
__device__ float g_ssp[BATCH * 768 * NSTRIP];
__device__ float g_inv[BATCH * 768];
__device__ float g_gpart[(size_t)GCH * BATCH * NH * CH * CH];
__device__ float g_attn[BATCH * NH * CH * CH];
__device__ __nv_bfloat16 g_A1[(size_t)C3 * KP];
__device__ __nv_bfloat16 g_xhi[(size_t)BATCH * DIM * HWD];
__device__ __nv_bfloat16 g_xlo[(size_t)BATCH * DIM * HWD];
__device__ __nv_bfloat16 g_vhi[(size_t)BATCH * DIM * HWD];
__device__ __nv_bfloat16 g_vlo[(size_t)BATCH * DIM * HWD];
__device__ __nv_bfloat16 g_Wbs[(size_t)BATCH * DIM * KP];

// ---------------------------------------------------------------------------
// sm_80-portable PTX helpers
// ---------------------------------------------------------------------------
__device__ __forceinline__ uint32_t smem_u32(const void* p) {
    uint32_t a;
    asm("{ .reg .u64 t; cvta.to.shared.u64 t, %1; cvt.u32.u64 %0, t; }" : "=r"(a) : "l"(p));
    return a;
}

__device__ __forceinline__ void cp16(uint32_t saddr, const void* gaddr) {
    asm volatile("cp.async.cg.shared.global [%0], [%1], 16;" :: "r"(saddr), "l"(gaddr));
}
#define CP_COMMIT() asm volatile("cp.async.commit_group;" ::: "memory")

__device__ __forceinline__ void ldmx4(uint32_t* r, uint32_t addr) {
    asm volatile("ldmatrix.sync.aligned.m8n8.x4.shared.b16 {%0,%1,%2,%3}, [%4];"
                 : "=r"(r[0]), "=r"(r[1]), "=r"(r[2]), "=r"(r[3]) : "r"(addr));
}

__device__ __forceinline__ void ldmx4t(uint32_t* r, uint32_t addr) {
    asm volatile("ldmatrix.sync.aligned.m8n8.x4.trans.shared.b16 {%0,%1,%2,%3}, [%4];"
                 : "=r"(r[0]), "=r"(r[1]), "=r"(r[2]), "=r"(r[3]) : "r"(addr));
}

__device__ __forceinline__ void mma16816(float* c, const uint32_t* a, const uint32_t* b) {
    asm volatile(
        "mma.sync.aligned.m16n8k16.row.col.f32.bf16.bf16.f32 "
        "{%0,%1,%2,%3}, {%4,%5,%6,%7}, {%8,%9}, {%0,%1,%2,%3};"
        : "+f"(c[0]), "+f"(c[1]), "+f"(c[2]), "+f"(c[3])
        : "r"(a[0]), "r"(a[1]), "r"(a[2]), "r"(a[3]), "r"(b[0]), "r"(b[1]));
}

// ---------------------------------------------------------------------------
// Split-precision bf16 tensor-core GEMM.
//   C[bz][m][n] = sum_{k'} A'[m][k'] * B'[n][seg(k')]
// A' rows [hi|lo|hi] (KP cols, K-major, as before).
// B source is K-MAJOR fp-split planes: Bhi/Blo [bz][384][HWD] bf16.
// Chunk c: seg = (c<12 ? hi : lo), k0 = (c%6)*64.
// B smem: 64 k-rows x 256B, unit u (16B) stored at (u ^ (k&7)); consumed via
// ldmatrix.x4.trans -> conflict-free.
// ---------------------------------------------------------------------------
__global__ void __launch_bounds__(256, 2)
gemm_split(const __nv_bfloat16* __restrict__ A, long aBatchStride,
           const __nv_bfloat16* __restrict__ Bhi,
           const __nv_bfloat16* __restrict__ Blo,
           float* __restrict__ C, long cBatchStride)
{
    extern __shared__ char sm[];
    const uint32_t smBase = smem_u32(sm);

    const int tid = threadIdx.x;
    const int wid = tid >> 5, l = tid & 31;
    const int wm = wid >> 2, wn = wid & 3;
    const int bm0 = blockIdx.x * BM;
    const int bn0 = blockIdx.y * BN;
    const int bz  = blockIdx.z;

    const __nv_bfloat16* Ab  = A + (long)bz * aBatchStride + (long)bm0 * KP;
    const __nv_bfloat16* Bhb = Bhi + (long)bz * DIM * HWD;
    const __nv_bfloat16* Blb = Blo + (long)bz * DIM * HWD;
    float* Cb = C + (long)bz * cBatchStride + (long)bm0 * HWD + bn0;

    const int ldr = tid >> 3, ldq = tid & 7;     // A loader mapping
    const int bro = tid >> 2, bu0 = tid & 3;     // B loader mapping

    auto load_chunk = [&](int c, int s) {
        const uint32_t sA = smBase + s * STAGE;
        const uint32_t sB = sA + ATILE;
        const __nv_bfloat16* ac = Ab + c * KC;
#pragma unroll
        for (int i = 0; i < 4; i++) {
            int r = ldr + i * 32;
            int u = ldq ^ (r & 7);
            cp16(sA + r * 128 + u * 16, ac + (long)r * KP + ldq * 8);
        }
        const __nv_bfloat16* bsrc = (c < 12) ? Bhb : Blb;
        const int k0 = (c % 6) * KC;
        const __nv_bfloat16* brow = bsrc + (long)(k0 + bro) * HWD + bn0;
#pragma unroll
        for (int i = 0; i < 4; i++) {
            int u = bu0 + 4 * i;
            cp16(sB + bro * 256 + ((u ^ (bro & 7)) * 16), brow + u * 8);
        }
        CP_COMMIT();
    };

    float acc[4][4][4] = {};

    const int l7 = l & 7;
    const int a_x = l >> 4;
    int arow[4];
#pragma unroll
    for (int mi = 0; mi < 4; mi++)
        arow[mi] = (wm * 64 + mi * 16 + (l & 15)) * 128;

    // B ldmatrix.trans per-lane components: row-in-chunk and n-unit
    const int b_row_l = l & 15;                   // k within 16-block
    const int b_u_l   = wn * 4 + (l >> 4);        // 16B n-unit (g adds +2)

    load_chunk(0, 0);
    load_chunk(1, 1);

    for (int c = 0; c < NCHUNK; c++) {
        if (c + 2 < NCHUNK) {
            asm volatile("cp.async.wait_group 1;" ::: "memory");
        } else {
            asm volatile("cp.async.wait_group 0;" ::: "memory");
        }
        __syncthreads();
        if (c + 2 < NCHUNK) load_chunk(c + 2, (c + 2) % NSTAGE);

        const int s = c % NSTAGE;
        const uint32_t sA = smBase + s * STAGE;
        const uint32_t sB = sA + ATILE;

#pragma unroll
        for (int kk = 0; kk < 4; kk++) {
            uint32_t afr[4][4];
#pragma unroll
            for (int mi = 0; mi < 4; mi++) {
                uint32_t u = (uint32_t)((kk * 2 + a_x) ^ l7);
                ldmx4(afr[mi], sA + arow[mi] + u * 16);
            }
            uint32_t bfr[4][2];
#pragma unroll
            for (int g = 0; g < 2; g++) {
                uint32_t t4[4];
                int row = kk * 16 + b_row_l;
                int u = b_u_l + g * 2;
                ldmx4t(t4, sB + row * 256 + ((u ^ (row & 7)) * 16));
                bfr[2 * g][0] = t4[0]; bfr[2 * g][1] = t4[1];
                bfr[2 * g + 1][0] = t4[2]; bfr[2 * g + 1][1] = t4[3];
            }
#pragma unroll
            for (int mi = 0; mi < 4; mi++)
#pragma unroll
                for (int ni = 0; ni < 4; ni++)
                    mma16816(acc[mi][ni], afr[mi], bfr[ni]);
        }
        __syncthreads();
    }

    const int crow = l >> 2, ccol = (l & 3) * 2;
#pragma unroll
    for (int mi = 0; mi < 4; mi++) {
#pragma unroll
        for (int ni = 0; ni < 4; ni++) {
            float* p = Cb + (long)(wm * 64 + mi * 16 + crow) * HWD + wn * 32 + ni * 8 + ccol;
            *(float2*)p = make_float2(acc[mi][ni][0], acc[mi][ni][1]);
            *(float2*)(p + 8L * HWD) = make_float2(acc[mi][ni][2], acc[mi][ni][3]);
        }
    }
}

// ---------------------------------------------------------------------------
// Split qkv_w -> A' [1152][1152] bf16 = [hi | lo | hi]
// ---------------------------------------------------------------------------
__global__ void split_w(const float* __restrict__ w, __nv_bfloat16* __restrict__ o)
{
    int idx = blockIdx.x * 256 + threadIdx.x;
    if (idx >= C3 * DIM) return;
    int m = idx / DIM, k = idx % DIM;
    float v = w[idx];
    __nv_bfloat16 hi = __float2bfloat16(v);
    __nv_bfloat16 lo = __float2bfloat16(v - __bfloat162float(hi));
    o[(long)m * KP + k]       = hi;
    o[(long)m * KP + 384 + k] = lo;
    o[(long)m * KP + 768 + k] = hi;
}

// ---------------------------------------------------------------------------
// split_c: fp32 [b][384][HWD] -> hi/lo bf16 planes, same layout (no transpose)
// ---------------------------------------------------------------------------
__global__ void __launch_bounds__(256)
split_c(const float* __restrict__ src, __nv_bfloat16* __restrict__ hi,
        __nv_bfloat16* __restrict__ lo)
{
    long i4 = (long)blockIdx.x * 256 + threadIdx.x;   // float4 index
    float4 v = ((const float4*)src)[i4];
    __nv_bfloat16 hx = __float2bfloat16(v.x);
    __nv_bfloat16 hy = __float2bfloat16(v.y);
    __nv_bfloat16 hz = __float2bfloat16(v.z);
    __nv_bfloat16 hw = __float2bfloat16(v.w);
    __nv_bfloat162 h01, h23, l01, l23;
    h01.x = hx; h01.y = hy; h23.x = hz; h23.y = hw;
    l01.x = __float2bfloat16(v.x - __bfloat162float(hx));
    l01.y = __float2bfloat16(v.y - __bfloat162float(hy));
    l23.x = __float2bfloat16(v.z - __bfloat162float(hz));
    l23.y = __float2bfloat16(v.w - __bfloat162float(hw));
    ((__nv_bfloat162*)hi)[i4 * 2]     = h01;
    ((__nv_bfloat162*)hi)[i4 * 2 + 1] = h23;
    ((__nv_bfloat162*)lo)[i4 * 2]     = l01;
    ((__nv_bfloat162*)lo)[i4 * 2 + 1] = l23;
}

// ---------------------------------------------------------------------------
// Depthwise 3x3 v6: as v5, but v channels write hi/lo bf16 planes directly
// (K-major layout for the GEMM) instead of fp32; q/k channels unchanged.
// ---------------------------------------------------------------------------
__global__ void __launch_bounds__(256)
dwconv3(const float* __restrict__ in, const float* __restrict__ w,
        float* __restrict__ out, float* __restrict__ ssp,
        __nv_bfloat16* __restrict__ vhi, __nv_bfloat16* __restrict__ vlo)
{
    __shared__ float pl[(SROWS + 2) * SPITCH];
    __shared__ float red[256];

    const int strip = blockIdx.x & (NSTRIP - 1);
    const int c = (blockIdx.x >> 2) % C3;
    const int b = blockIdx.x / (NSTRIP * C3);
    const int tid = threadIdx.x;

#pragma unroll
    for (int i = tid; i < (SROWS + 2) * SPITCH; i += 256)
        pl[i] = 0.f;
    __syncthreads();

    const int r0 = strip * SROWS;
    const float* ip = in + ((long)b * C3 + c) * HWD;

    {
        const int rlo = (strip == 0) ? 1 : 0;
        const int rhi = (strip == NSTRIP - 1) ? SROWS : SROWS + 1;
        const int njobs = (rhi - rlo + 1) * 32;
        for (int i = tid; i < njobs; i += 256) {
            int lr = rlo + (i >> 5);
            int x4 = (i & 31) * 4;
            *(float4*)&pl[lr * SPITCH + 4 + x4] =
                *(const float4*)&ip[(long)(r0 - 1 + lr) * 128 + x4];
        }
    }

    const float* wp = w + c * 9;
    float w0 = wp[0], w1 = wp[1], w2 = wp[2];
    float w3 = wp[3], w4 = wp[4], w5 = wp[5];
    float w6 = wp[6], w7 = wp[7], w8 = wp[8];
    __syncthreads();

    const int tx = tid & 31, ty = tid >> 5;
    const int x4 = tx * 4;
    const int h0 = ty * 4;

    float4 Ar[3], Br[3], Cr[3];
    auto loadrow = [&](int srow, int slot) {
        int idx = srow * SPITCH + 4 + x4;
        Ar[slot] = *(float4*)&pl[idx - 4];
        Br[slot] = *(float4*)&pl[idx];
        Cr[slot] = *(float4*)&pl[idx + 4];
    };
    loadrow(h0 + 0, 0);
    loadrow(h0 + 1, 1);
    loadrow(h0 + 2, 2);

    const bool isV = (c >= 768);
    float4* op4 = (float4*)(out + ((long)b * C3 + c) * HWD + (long)r0 * 128);
    __nv_bfloat162* vh2 = nullptr;
    __nv_bfloat162* vl2 = nullptr;
    if (isV) {
        long off = ((long)b * DIM + (c - 768)) * HWD + (long)r0 * 128;
        vh2 = (__nv_bfloat162*)(vhi + off);
        vl2 = (__nv_bfloat162*)(vlo + off);
    }
    float ss = 0.f;

#pragma unroll
    for (int i = 0; i < 4; i++) {
        const int s0 = i % 3, s1 = (i + 1) % 3, s2 = (i + 2) % 3;
        float4 s;
        s.x = w0 * Ar[s0].w + w1 * Br[s0].x + w2 * Br[s0].y
            + w3 * Ar[s1].w + w4 * Br[s1].x + w5 * Br[s1].y
            + w6 * Ar[s2].w + w7 * Br[s2].x + w8 * Br[s2].y;
        s.y = w0 * Br[s0].x + w1 * Br[s0].y + w2 * Br[s0].z
            + w3 * Br[s1].x + w4 * Br[s1].y + w5 * Br[s1].z
            + w6 * Br[s2].x + w7 * Br[s2].y + w8 * Br[s2].z;
        s.z = w0 * Br[s0].y + w1 * Br[s0].z + w2 * Br[s0].w
            + w3 * Br[s1].y + w4 * Br[s1].z + w5 * Br[s1].w
            + w6 * Br[s2].y + w7 * Br[s2].z + w8 * Br[s2].w;
        s.w = w0 * Br[s0].z + w1 * Br[s0].w + w2 * Cr[s0].x
            + w3 * Br[s1].z + w4 * Br[s1].w + w5 * Cr[s1].x
            + w6 * Br[s2].z + w7 * Br[s2].w + w8 * Cr[s2].x;
        if (isV) {
            int e2 = (h0 + i) * 64 + tx * 2;
            __nv_bfloat16 hx = __float2bfloat16(s.x);
            __nv_bfloat16 hy = __float2bfloat16(s.y);
            __nv_bfloat16 hz = __float2bfloat16(s.z);
            __nv_bfloat16 hw = __float2bfloat16(s.w);
            __nv_bfloat162 h01, h23, l01, l23;
            h01.x = hx; h01.y = hy; h23.x = hz; h23.y = hw;
            l01.x = __float2bfloat16(s.x - __bfloat162float(hx));
            l01.y = __float2bfloat16(s.y - __bfloat162float(hy));
            l23.x = __float2bfloat16(s.z - __bfloat162float(hz));
            l23.y = __float2bfloat16(s.w - __bfloat162float(hw));
            vh2[e2] = h01; vh2[e2 + 1] = h23;
            vl2[e2] = l01; vl2[e2 + 1] = l23;
        } else {
            op4[(h0 + i) * 32 + tx] = s;
            ss += s.x * s.x + s.y * s.y + s.z * s.z + s.w * s.w;
        }
        if (i < 3) loadrow(h0 + 3 + i, s0);
    }

    if (c < 768) {
        red[tid] = ss;
        __syncthreads();
        for (int st = 128; st > 0; st >>= 1) {
            if (tid < st) red[tid] += red[tid + st];
            __syncthreads();
        }
        if (tid == 0)
            ssp[(b * 768 + c) * NSTRIP + strip] = red[0];
    }
}

// finalize inv norms from strip partials
__global__ void norm_fin(const float* __restrict__ ssp, float* __restrict__ inv)
{
    int i = blockIdx.x * 256 + threadIdx.x;
    if (i >= BATCH * 768) return;
    float s = 0.f;
#pragma unroll
    for (int j = 0; j < NSTRIP; j++) s += ssp[i * NSTRIP + j];
    inv[i] = 1.f / fmaxf(sqrtf(s), 1e-12f);
}

// ---------------------------------------------------------------------------
// Gram partial (unchanged)
// ---------------------------------------------------------------------------
__global__ void __launch_bounds__(256)
gram_partial(const float* __restrict__ qkv2, float* __restrict__ gpart)
{
    const int chunk = blockIdx.x;
    const int bh = blockIdx.y;
    const int b = bh >> 3, h = bh & 7;
    const float* qb = qkv2 + ((long)b * C3 + h * CH) * HWD;
    const float* kb = qb + (long)DIM * HWD;

    __shared__ float qs[64][49], ks[64][49];
    const int tid = threadIdx.x;
    const int tx = tid & 15, ty = tid >> 4;
    float acc[3][3] = {};

    const int n0 = chunk * 512;
    for (int slab = 0; slab < 8; slab++) {
        const int base = n0 + slab * 64;
        __syncthreads();
#pragma unroll
        for (int j = 0; j < 3; j++) {
            int id = tid + j * 256;
            int rid = id >> 4, c4 = id & 15;
            float4 v = *(const float4*)(qb + (long)rid * HWD + base + c4 * 4);
            qs[c4 * 4 + 0][rid] = v.x; qs[c4 * 4 + 1][rid] = v.y;
            qs[c4 * 4 + 2][rid] = v.z; qs[c4 * 4 + 3][rid] = v.w;
            float4 u = *(const float4*)(kb + (long)rid * HWD + base + c4 * 4);
            ks[c4 * 4 + 0][rid] = u.x; ks[c4 * 4 + 1][rid] = u.y;
            ks[c4 * 4 + 2][rid] = u.z; ks[c4 * 4 + 3][rid] = u.w;
        }
        __syncthreads();
#pragma unroll 8
        for (int t = 0; t < 64; t++) {
            float qa[3], ka[3];
#pragma unroll
            for (int i = 0; i < 3; i++) qa[i] = qs[t][ty * 3 + i];
#pragma unroll
            for (int j = 0; j < 3; j++) ka[j] = ks[t][tx * 3 + j];
#pragma unroll
            for (int i = 0; i < 3; i++)
#pragma unroll
                for (int j = 0; j < 3; j++)
                    acc[i][j] += qa[i] * ka[j];
        }
    }
    float* op = gpart + ((long)chunk * 64 + bh) * (CH * CH);
#pragma unroll
    for (int i = 0; i < 3; i++)
#pragma unroll
        for (int j = 0; j < 3; j++)
            op[(ty * 3 + i) * CH + tx * 3 + j] = acc[i][j];
}

__global__ void gram_scale(const float* __restrict__ gpart, const float* __restrict__ inv,
                           const float* __restrict__ temp, float* __restrict__ attn)
{
    int idx = blockIdx.x * 256 + threadIdx.x;
    if (idx >= 64 * CH * CH) return;
    int bh = idx / (CH * CH), r = idx % (CH * CH);
    int c = r / CH, d = r % CH;
    int b = bh >> 3, h = bh & 7;
    float s = 0.f;
#pragma unroll
    for (int ck = 0; ck < GCH; ck++) s += gpart[((long)ck * 64 + bh) * (CH * CH) + r];
    float iq = inv[b * 768 + h * CH + c];
    float ik = inv[b * 768 + 384 + h * CH + d];
    attn[idx] = s * iq * ik * temp[h];
}

__global__ void topk_softmax(float* __restrict__ attn)
{
    int row = blockIdx.x;
    float* p = attn + (long)row * CH;
    __shared__ float s[CH], e[CH];
    int i = threadIdx.x;
    if (i < CH) s[i] = p[i];
    __syncthreads();
    if (i < CH) {
        float v = s[i];
        int cnt = 0;
        float m = -1e30f;
#pragma unroll
        for (int j = 0; j < CH; j++) {
            cnt += (s[j] > v);
            m = fmaxf(m, s[j]);
        }
        e[i] = (cnt < TOPKN) ? expf(v - m) : 0.f;
    }
    __syncthreads();
    if (i < CH) {
        float sum = 0.f;
#pragma unroll
        for (int j = 0; j < CH; j++) sum += e[j];
        p[i] = e[i] / sum;
    }
}

// ---------------------------------------------------------------------------
// Fold proj_w @ blockdiag(attn) -> Wbs (bf16 split [hi|lo|hi])
// ---------------------------------------------------------------------------
__global__ void fold_proj(const float* __restrict__ projw, const float* __restrict__ attn,
                          __nv_bfloat16* __restrict__ Wbs)
{
    int idx = blockIdx.x * 256 + threadIdx.x;
    if (idx >= BATCH * DIM * DIM) return;
    int b = idx / (DIM * DIM);
    int r = idx % (DIM * DIM);
    int o = r / DIM, dg = r % DIM;
    int h = dg / CH, d = dg % CH;
    const float* pw = projw + o * DIM + h * CH;
    const float* at = attn + ((long)(b * NH + h) * CH) * CH + d;
    float s = 0.f;
#pragma unroll
    for (int c = 0; c < CH; c++) s += pw[c] * at[c * CH];
    __nv_bfloat16 hi = __float2bfloat16(s);
    __nv_bfloat16 lo = __float2bfloat16(s - __bfloat162float(hi));
    __nv_bfloat16* row = Wbs + ((long)b * DIM + o) * KP;
    row[dg]       = hi;
    row[384 + dg] = lo;
    row[768 + dg] = hi;
}

// ---------------------------------------------------------------------------
extern "C" void kernel_launch(void* const* d_in, const int* in_sizes, int n_in,
                              void* d_out, int out_size)
{
    const float* x      = (const float*)d_in[0];
    const float* qkv_w  = (const float*)d_in[1];
    const float* dw_w   = (const float*)d_in[2];
    const float* proj_w = (const float*)d_in[3];
    const float* temp   = (const float*)d_in[4];
    float* out = (float*)d_out;

    float *qkv1, *qkv2, *ssp, *inv, *gpart, *attn;
    __nv_bfloat16 *A1, *xhi, *xlo, *vhi, *vlo, *Wbs;
    cudaGetSymbolAddress((void**)&qkv1,  g_qkv1);
    cudaGetSymbolAddress((void**)&qkv2,  g_qkv2);
    cudaGetSymbolAddress((void**)&ssp,   g_ssp);
    cudaGetSymbolAddress((void**)&inv,   g_inv);
    cudaGetSymbolAddress((void**)&gpart, g_gpart);
    cudaGetSymbolAddress((void**)&attn,  g_attn);
    cudaGetSymbolAddress((void**)&A1,    g_A1);
    cudaGetSymbolAddress((void**)&xhi,   g_xhi);
    cudaGetSymbolAddress((void**)&xlo,   g_xlo);
    cudaGetSymbolAddress((void**)&vhi,   g_vhi);
    cudaGetSymbolAddress((void**)&vlo,   g_vlo);
    cudaGetSymbolAddress((void**)&Wbs,   g_Wbs);

    cudaFuncSetAttribute(gemm_split, cudaFuncAttributeMaxDynamicSharedMemorySize, GEMM_SMEM);

    // 0) operand prep (no transposes)
    split_w<<<(C3 * DIM + 255) / 256, 256>>>(qkv_w, A1);
    split_c<<<(int)(((long)BATCH * DIM * HWD / 4) / 256), 256>>>(x, xhi, xlo);

    // 1) qkv = qkv_w @ x
    gemm_split<<<dim3(C3 / BM, HWD / BN, BATCH), 256, GEMM_SMEM>>>(
        A1, 0L, xhi, xlo, qkv1, (long)C3 * HWD);

    // 2) depthwise 3x3: q/k -> fp32 + norms, v -> bf16 hi/lo planes
    dwconv3<<<BATCH * C3 * NSTRIP, 256>>>(qkv1, dw_w, qkv2, ssp, vhi, vlo);
    norm_fin<<<(BATCH * 768 + 255) / 256, 256>>>(ssp, inv);

    // 3) Gram + scale
    gram_partial<<<dim3(GCH, BATCH * NH), 256>>>(qkv2, gpart);
    gram_scale<<<(64 * CH * CH + 255) / 256, 256>>>(gpart, inv, temp, attn);

    // 4) top-7 + softmax
    topk_softmax<<<BATCH * NH * CH, 64>>>(attn);

    // 5) fold proj @ blockdiag(attn)
    fold_proj<<<(BATCH * DIM * DIM + 255) / 256, 256>>>(proj_w, attn, Wbs);

    // 6) out = Wb @ v
    gemm_split<<<dim3(DIM / BM, HWD / BN, BATCH), 256, GEMM_SMEM>>>(
        Wbs, (long)DIM * KP, vhi, vlo, out, (long)DIM * HWD);
}